// round 15
// baseline (speedup 1.0000x reference)
#include <cuda_runtime.h>
#include <math.h>
#include <stdint.h>

// Problem constants
#define BB 8
#define HH 64
#define WW 64
#define CC 128
#define DD 128
#define LL 4096            // H*W
#define NPIX (BB*LL)       // 32768
#define NS 8               // D_STATE
#define RR 8               // DT_RANK

#define CS 64              // chunk size (steps)
#define NC (LL/CS)         // 64 chunks per batch

// Scratch (device globals; no allocations allowed)
__device__ float g_t1[NPIX*DD];
__device__ float g_xs[NPIX*DD];
__device__ float g_u0[NPIX*DD];
__device__ float g_z [NPIX*DD];
__device__ float g_u [NPIX*DD];
__device__ float g_dl[NPIX*DD];
__device__ float g_Bm[NPIX*NS];
__device__ float g_Cm[NPIX*NS];
__device__ float g_P [BB*NC*1024];
__device__ float g_hE[BB*NC*1024];
__device__ float g_h0[BB*NC*1024];
// fragment-packed tf32 hi/lo weights: float4 {bh0, bh1, bl0, bl1} per (tile,k,lane)
__device__ float g_wip[65536];   // in_proj: 32 tiles x 16 k x 32 lanes
__device__ float g_wop[32768];   // out_proj: 16 tiles x 16 k x 32 lanes
__device__ float g_w2p[8192];    // w2 gate: 16 tiles x 4 k x 32 lanes
__device__ float g_wtp[8192];    // wout:    16 tiles x 4 k x 32 lanes
__device__ float g_wxp[6144];    // x_proj:  3 tiles x 16 k x 32 lanes

__device__ __forceinline__ float siluf(float v){ return v / (1.f + __expf(-v)); }

__device__ __forceinline__ uint32_t f2tf(float x){
    uint32_t r; asm("cvt.rna.tf32.f32 %0, %1;" : "=r"(r) : "f"(x)); return r;
}
__device__ __forceinline__ void mma8(float4& c, uint32_t a0, uint32_t a1, uint32_t a2, uint32_t a3,
                                     uint32_t b0, uint32_t b1){
    asm volatile("mma.sync.aligned.m16n8k8.row.col.f32.tf32.tf32.f32 "
                 "{%0,%1,%2,%3},{%4,%5,%6,%7},{%8,%9},{%0,%1,%2,%3};\n"
                 : "+f"(c.x), "+f"(c.y), "+f"(c.z), "+f"(c.w)
                 : "r"(a0), "r"(a1), "r"(a2), "r"(a3), "r"(b0), "r"(b1));
}
__device__ __forceinline__ void ldsm4(uint32_t& r0, uint32_t& r1, uint32_t& r2, uint32_t& r3,
                                      uint32_t addr){
    asm volatile("ldmatrix.sync.aligned.m8n8.x4.shared.b16 {%0,%1,%2,%3}, [%4];"
                 : "=r"(r0), "=r"(r1), "=r"(r2), "=r"(r3) : "r"(addr));
}
__device__ __forceinline__ float4 pack_hl(float v0, float v1){
    float h0 = __uint_as_float(f2tf(v0));
    float h1 = __uint_as_float(f2tf(v1));
    return make_float4(h0, h1, v0 - h0, v1 - h1);
}

// ---------------------------------------------------------------- K0: weight fragment-pack prep
__global__ void k_prep(const float* __restrict__ wi, const float* __restrict__ wo,
                       const float* __restrict__ w2, const float* __restrict__ wt,
                       const float* __restrict__ wx,
                       float* wip, float* wop, float* w2p, float* wtp, float* wxp){
    int i = blockIdx.x * 256 + threadIdx.x;
    if (i >= 30208) return;
    if (i < 16384){
        int lane = i & 31, k = (i >> 5) & 15, tile = i >> 9;
        int row = lane >> 2, col = lane & 3;
        int e = tile*8 + row, kc = k*8 + col;
        ((float4*)wip)[i] = pack_hl(wi[e*128 + kc], wi[e*128 + kc + 4]);
    } else if (i < 24576){
        int j = i - 16384;
        int lane = j & 31, k = (j >> 5) & 15, tile = j >> 9;
        int row = lane >> 2, col = lane & 3;
        int e = tile*8 + row, kc = k*8 + col;
        ((float4*)wop)[j] = pack_hl(wo[e*128 + kc], wo[e*128 + kc + 4]);
    } else if (i < 26624){
        int j = i - 24576;
        int lane = j & 31, k = (j >> 5) & 3, tile = j >> 7;
        int row = lane >> 2, col = lane & 3;
        int e = tile*8 + row;
        ((float4*)w2p)[j] = pack_hl(w2[e*32 + k*8 + col], w2[e*32 + k*8 + col + 4]);
    } else if (i < 28672){
        int j = i - 26624;
        int lane = j & 31, k = (j >> 5) & 3, tile = j >> 7;
        int row = lane >> 2, col = lane & 3;
        int e = tile*8 + row;
        ((float4*)wtp)[j] = pack_hl(wt[e*32 + k*8 + col], wt[e*32 + k*8 + col + 4]);
    } else {
        int j = i - 28672;
        int lane = j & 31, k = (j >> 5) & 15, tile = j >> 9;
        int row = lane >> 2, col = lane & 3;
        int e = tile*8 + row, kc = k*8 + col;
        ((float4*)wxp)[j] = pack_hl(wx[e*128 + kc], wx[e*128 + kc + 4]);
    }
}

// ---------------------------------------------------------------- K1: grouped 1x1
__global__ void __launch_bounds__(256) k_g1(const float* __restrict__ x,
                                            const float* __restrict__ w,
                                            float* __restrict__ out){
    __shared__ float xt[32*128];
    int pix0 = blockIdx.x * 32;
    const float4* x4 = (const float4*)(x + (size_t)pix0*128);
    for (int i = threadIdx.x; i < 32*32; i += 256) ((float4*)xt)[i] = x4[i];
    __syncthreads();
    int t = threadIdx.x;
    int c = t & 127, half = t >> 7;
    int g = c >> 5;
    float4 wr[8];
#pragma unroll
    for (int i = 0; i < 8; i++) wr[i] = ((const float4*)(w + c*32))[i];
    const float* xb = xt + (half*16)*128 + g*32;
    float* ob = out + ((size_t)pix0 + half*16)*128 + c;
#pragma unroll
    for (int p = 0; p < 16; p++){
        const float* xr = xb + p*128;
        float a = 0.f;
#pragma unroll
        for (int i = 0; i < 8; i++){
            float4 xv = *(const float4*)(xr + i*4);
            a = fmaf(wr[i].x, xv.x, a); a = fmaf(wr[i].y, xv.y, a);
            a = fmaf(wr[i].z, xv.z, a); a = fmaf(wr[i].w, xv.w, a);
        }
        ob[(size_t)p*128] = a;
    }
}

// ---------------------------------------------------------------- K2: depthwise 3x3 + silu
__global__ void k_dw(const float* __restrict__ t1, const float* __restrict__ dw,
                     float* __restrict__ out){
    int idx = blockIdx.x * 256 + threadIdx.x;
    int d4 = idx & 31; int pix = idx >> 5;
    int wc = pix & 63; int h = (pix >> 6) & 63; int b = pix >> 12;
    int d = d4 << 2;
    float4 acc = make_float4(0.f, 0.f, 0.f, 0.f);
#pragma unroll
    for (int kh = 0; kh < 3; kh++){
        int hh = h + kh - 1; if (hh < 0 || hh >= 64) continue;
#pragma unroll
        for (int kw = 0; kw < 3; kw++){
            int ww = wc + kw - 1; if (ww < 0 || ww >= 64) continue;
            float4 tv = *(const float4*)(t1 + (((b*64 + hh)*64 + ww) << 7) + d);
            float4 wv = *(const float4*)(dw + (kh*3 + kw)*128 + d);
            acc.x = fmaf(tv.x, wv.x, acc.x); acc.y = fmaf(tv.y, wv.y, acc.y);
            acc.z = fmaf(tv.z, wv.z, acc.z); acc.w = fmaf(tv.w, wv.w, acc.w);
        }
    }
    float4 r; r.x = siluf(acc.x); r.y = siluf(acc.y); r.z = siluf(acc.z); r.w = siluf(acc.w);
    *(float4*)(out + (size_t)pix*128 + d) = r;
}

// ---------------------------------------------------------------- K3: in_proj via tf32 mma (round-13 config: ldmatrix A, 2x2 tiles)
// 512 thr, 128 pixels/block, 256 blocks. warp = (mp 0..3: 32 px, nq 0..3: 2 tiles/g)
__global__ void __launch_bounds__(512, 2) k_inproj(const float* __restrict__ xs,
                       const float* __restrict__ wip,
                       float* __restrict__ ub, float* __restrict__ zb){
    extern __shared__ float sm[];
    float* xt = sm;              // 128*132
    int tid = threadIdx.x;
    int pix0 = blockIdx.x * 128;
    {
        const float4* xs4 = (const float4*)(xs + (size_t)pix0*128);
        for (int i = tid; i < 128*32; i += 512){
            int p = i >> 5, q = i & 31;
            float4 v = xs4[i];
            v.x = __uint_as_float(f2tf(v.x)); v.y = __uint_as_float(f2tf(v.y));
            v.z = __uint_as_float(f2tf(v.z)); v.w = __uint_as_float(f2tf(v.w));
            *(float4*)(xt + p*132 + q*4) = v;
        }
    }
    __syncthreads();
    int warp = tid >> 5, lane = tid & 31;
    int row_ = lane >> 2, col_ = lane & 3;
    int mp = warp >> 2, nq = warp & 3;
    int m0 = mp * 32;
    int lr = lane & 15, lc = (lane >> 4) << 2;
    uint32_t xtb = (uint32_t)__cvta_generic_to_shared(xt);
    uint32_t aad0 = xtb + (((m0 + lr)*132 + lc) << 2);
    uint32_t aad1 = aad0 + (16*132 << 2);
    const float4* wip4 = (const float4*)wip;
#pragma unroll 1
    for (int g = 0; g < 4; g++){
        float4 acc[2][2];
#pragma unroll
        for (int mm = 0; mm < 2; mm++)
#pragma unroll
            for (int tt = 0; tt < 2; tt++) acc[mm][tt] = make_float4(0.f,0.f,0.f,0.f);
#pragma unroll 4
        for (int k = 0; k < 16; k++){
            uint32_t a0, a1, a2, a3, c0, c1, c2, c3;
            ldsm4(a0, a1, a2, a3, aad0 + k*32);
            ldsm4(c0, c1, c2, c3, aad1 + k*32);
#pragma unroll
            for (int tt = 0; tt < 2; tt++){
                int tile = g*8 + nq*2 + tt;
                float4 bw = __ldg(wip4 + tile*512 + k*32 + lane);
                uint32_t bh0 = __float_as_uint(bw.x), bh1 = __float_as_uint(bw.y);
                uint32_t bl0 = __float_as_uint(bw.z), bl1 = __float_as_uint(bw.w);
                mma8(acc[0][tt], a0, a1, a2, a3, bh0, bh1);
                mma8(acc[0][tt], a0, a1, a2, a3, bl0, bl1);
                mma8(acc[1][tt], c0, c1, c2, c3, bh0, bh1);
                mma8(acc[1][tt], c0, c1, c2, c3, bl0, bl1);
            }
        }
#pragma unroll
        for (int mm = 0; mm < 2; mm++){
            int pixA = pix0 + m0 + mm*16 + row_;
            int pixB = pixA + 8;
#pragma unroll
            for (int tt = 0; tt < 2; tt++){
                int e0 = g*64 + (nq*2 + tt)*8 + 2*col_;
                float* basep = (g < 2) ? (ub + e0) : (zb + e0 - 128);
                *(float2*)(basep + (size_t)pixA*128) = make_float2(acc[mm][tt].x, acc[mm][tt].y);
                *(float2*)(basep + (size_t)pixB*128) = make_float2(acc[mm][tt].z, acc[mm][tt].w);
            }
        }
    }
}

// ---------------------------------------------------------------- K4: fused conv1d + x_proj(mma) + dt_proj + scanA
#define XDS 26
__global__ void __launch_bounds__(512, 2) k_cxp2(const float* __restrict__ u0,
                        const float* __restrict__ cw, const float* __restrict__ cb,
                        const float* __restrict__ wxp,
                        const float* __restrict__ dtw, const float* __restrict__ dtb,
                        const float* __restrict__ A_log,
                        float* __restrict__ ug,
                        float* __restrict__ dl, float* __restrict__ Bb, float* __restrict__ Cb,
                        float* __restrict__ Pg, float* __restrict__ hEg){
    extern __shared__ float sm[];
    float* u0s = sm;                 // 66*128 = 8448 ; aliased by sdl after conv
    float* su  = sm + 8448;          // 64*132
    float* xd  = sm + 16896;         // 64*XDS
    float* sdl = u0s;
    int pix0 = blockIdx.x * 64;
    int b = blockIdx.x >> 6;
    int c = blockIdx.x & 63;
    int l0 = pix0 & (LL - 1);
    int t = threadIdx.x, warp = t >> 5, lane = t & 31;
    {
        const float4* u4 = (const float4*)(u0 + ((size_t)pix0 - 2)*128);
        for (int i = t; i < 66*32; i += 512){
            int p = i >> 5;
            float4 v = make_float4(0.f,0.f,0.f,0.f);
            if (!(l0 == 0 && p < 2)) v = u4[i];
            ((float4*)u0s)[i] = v;
        }
    }
    __syncthreads();
    {
        int d = t & 127, ph = t >> 7;
        float w0 = cw[d*3], w1c = cw[d*3 + 1], w2c = cw[d*3 + 2];
        float bias = cb[d];
#pragma unroll 4
        for (int p = ph*16; p < ph*16 + 16; p++){
            float a = fmaf(w2c, u0s[(p + 2)*128 + d],
                      fmaf(w1c, u0s[(p + 1)*128 + d],
                      fmaf(w0,  u0s[p*128 + d], bias)));
            a = siluf(a);
            ug[(size_t)(pix0 + p)*128 + d] = a;
            su[p*132 + d] = a;
        }
    }
    __syncthreads();
    if (warp < 12){
        int m0 = (warp & 3) * 16;
        int ntile = warp >> 2;
        int row_ = lane >> 2, col_ = lane & 3;
        int lr = lane & 15, lc = (lane >> 4) << 2;
        uint32_t sub = (uint32_t)__cvta_generic_to_shared(su);
        uint32_t aad = sub + (((m0 + lr)*132 + lc) << 2);
        const float4* wxp4 = (const float4*)wxp;
        float4 acc = make_float4(0.f,0.f,0.f,0.f);
#pragma unroll 2
        for (int k = 0; k < 16; k++){
            uint32_t u0_, u1_, u2_, u3_;
            ldsm4(u0_, u1_, u2_, u3_, aad + k*32);
            float f0 = __uint_as_float(u0_), f1 = __uint_as_float(u1_);
            float f2 = __uint_as_float(u2_), f3 = __uint_as_float(u3_);
            uint32_t h0 = f2tf(f0), h1 = f2tf(f1), h2 = f2tf(f2), h3 = f2tf(f3);
            uint32_t l0_ = __float_as_uint(f0 - __uint_as_float(h0));
            uint32_t l1  = __float_as_uint(f1 - __uint_as_float(h1));
            uint32_t l2  = __float_as_uint(f2 - __uint_as_float(h2));
            uint32_t l3  = __float_as_uint(f3 - __uint_as_float(h3));
            float4 bw = __ldg(wxp4 + (ntile*16 + k)*32 + lane);
            uint32_t bh0 = __float_as_uint(bw.x), bh1 = __float_as_uint(bw.y);
            uint32_t bl0 = __float_as_uint(bw.z), bl1 = __float_as_uint(bw.w);
            mma8(acc, h0, h1, h2, h3, bh0, bh1);
            mma8(acc, h0, h1, h2, h3, bl0, bl1);
            mma8(acc, l0_, l1, l2, l3, bh0, bh1);
        }
        int pA = m0 + row_, pB = pA + 8;
        int cc = ntile*8 + 2*col_;
        *(float2*)(xd + pA*XDS + cc) = make_float2(acc.x, acc.y);
        *(float2*)(xd + pB*XDS + cc) = make_float2(acc.z, acc.w);
    }
    __syncthreads();
    {
        int d = t & 127, ph = t >> 7;
        float4 wa = ((const float4*)(dtw + d*8))[0];
        float4 wb = ((const float4*)(dtw + d*8))[1];
        float bias = dtb[d];
#pragma unroll 4
        for (int p = ph*16; p < ph*16 + 16; p++){
            const float* xr = xd + p*XDS;
            float a = bias;
            a = fmaf(xr[0], wa.x, a); a = fmaf(xr[1], wa.y, a);
            a = fmaf(xr[2], wa.z, a); a = fmaf(xr[3], wa.w, a);
            a = fmaf(xr[4], wb.x, a); a = fmaf(xr[5], wb.y, a);
            a = fmaf(xr[6], wb.z, a); a = fmaf(xr[7], wb.w, a);
            float sp = (a > 20.f) ? a : log1pf(__expf(a));
            dl[(size_t)(pix0 + p)*128 + d] = sp;
            sdl[p*128 + d] = sp;
        }
    }
    {
        int p = t >> 3, n = t & 7;
        Bb[(pix0 + p)*8 + n] = xd[p*XDS + 8 + n];
        Cb[(pix0 + p)*8 + n] = xd[p*XDS + 16 + n];
    }
    __syncthreads();
    {
        int d = t >> 2, np = (t & 3) * 2;
        float Av0 = -__expf(A_log[d*8 + np]);
        float Av1 = -__expf(A_log[d*8 + np + 1]);
        float h0 = 0.f, h1 = 0.f, P0 = 1.f, P1 = 1.f;
#pragma unroll 4
        for (int l = 0; l < CS; l++){
            float de = sdl[l*128 + d];
            float uu = su[l*132 + d];
            float du = de * uu;
            float2 Bv = *(const float2*)(xd + l*XDS + 8 + np);
            float dA0 = __expf(de * Av0);
            float dA1 = __expf(de * Av1);
            P0 *= dA0; P1 *= dA1;
            h0 = fmaf(dA0, h0, du * Bv.x);
            h1 = fmaf(dA1, h1, du * Bv.y);
        }
        size_t oidx = (size_t)(b*NC + c)*1024 + d*8 + np;
        *(float2*)(Pg + oidx) = make_float2(P0, P1);
        *(float2*)(hEg + oidx) = make_float2(h0, h1);
    }
}

// ---------------------------------------------------------------- K5: chunk combine
__global__ void k_scanB(const float* __restrict__ Pg, const float* __restrict__ hEg,
                        float* __restrict__ h0g){
    int j = blockIdx.x * 128 + threadIdx.x;
    int b = j >> 10, dn = j & 1023;
    float h = 0.f;
#pragma unroll 8
    for (int c = 0; c < NC; c++){
        int idx = (b*NC + c)*1024 + dn;
        h0g[idx] = h;
        h = fmaf(Pg[idx], h, hEg[idx]);
    }
}

// ---------------------------------------------------------------- K6: MEGA2 = scanC + out_proj + LN + gate GEMMs
// smem 104.5 KB -> 2 blocks/SM; scan reads dl/u direct from gmem (L1).
__global__ void __launch_bounds__(512, 2) k_mega2(
        const float* __restrict__ dl, const float* __restrict__ u,
        const float* __restrict__ z, const float* __restrict__ Bb,
        const float* __restrict__ Cb, const float* __restrict__ A_log,
        const float* __restrict__ Dp, const float* __restrict__ h0g,
        const float* __restrict__ wop,
        const float* __restrict__ gamma, const float* __restrict__ beta,
        const float* __restrict__ x,
        const float* __restrict__ w2p, const float* __restrict__ wtp,
        float* __restrict__ out){
    extern __shared__ float sm[];
    float* xt  = sm;              // 8448 (used phase 6+)
    float* r3  = sm + 8448;       // 8448: y -> fs
    float* mt  = sm + 16896;      // 8448
    float* sB  = sm + 25344;      // 512
    float* sC  = sB + 512;        // 512
    float* mus = sC + 512;        // 64
    float* rss = mus + 64;        // 64
    float* gb  = rss + 64;        // 256
    const float4* wop4 = (const float4*)wop;
    const float4* w2p4 = (const float4*)w2p;
    const float4* wtp4 = (const float4*)wtp;
    int b = blockIdx.x >> 6;
    int c = blockIdx.x & (NC - 1);
    int t = threadIdx.x, warp = t >> 5, lane = t & 31;
    int row_ = lane >> 2, col_ = lane & 3;
    int lr = lane & 15, lc = (lane >> 4) << 2;
    int pix0 = b*LL + c*CS;
    size_t base = (size_t)pix0*128;
    // phase 1: stage B/C + gamma/beta
    {
        int nb = pix0*8;
        if (t < CS*8){ sB[t] = Bb[nb + t]; sC[t] = Cb[nb + t]; }
        if (t < 128){ gb[t] = gamma[t]; gb[128 + t] = beta[t]; }
    }
    __syncthreads();
    // phase 2: scan (dl/u via L1)
    {
        int d = t >> 2, np = (t & 3) * 2;
        float Av0 = -__expf(A_log[d*8 + np]);
        float Av1 = -__expf(A_log[d*8 + np + 1]);
        float2 h = *(const float2*)(h0g + (size_t)(b*NC + c)*1024 + d*8 + np);
        const float* dlp = dl + base + d;
        const float* up  = u + base + d;
#pragma unroll 4
        for (int l = 0; l < CS; l++){
            float de = __ldg(dlp + l*128);
            float uu = __ldg(up + l*128);
            float du = de * uu;
            float2 Bv = *(const float2*)(sB + l*8 + np);
            float2 Cv = *(const float2*)(sC + l*8 + np);
            h.x = fmaf(__expf(de * Av0), h.x, du * Bv.x);
            h.y = fmaf(__expf(de * Av1), h.y, du * Bv.y);
            float y = h.x * Cv.x + h.y * Cv.y;
            y += __shfl_xor_sync(0xffffffffu, y, 1);
            y += __shfl_xor_sync(0xffffffffu, y, 2);
            if ((t & 3) == 0) r3[l*132 + d] = y;
        }
    }
    __syncthreads();
    // phase 3: y + u*D, gate silu(z), tf32
    {
        for (int i = t; i < CS*128; i += 512){
            int l = i >> 7, d = i & 127;
            float val = fmaf(__ldg(u + base + i), Dp[d], r3[l*132 + d]);
            val *= siluf(z[base + i]);
            r3[l*132 + d] = __uint_as_float(f2tf(val));
        }
    }
    __syncthreads();
    // phase 5: out_proj GEMM
    {
        int mp = warp >> 3, tp = warp & 7;
        int m0 = mp * 32;
        uint32_t r3b = (uint32_t)__cvta_generic_to_shared(r3);
        uint32_t yad0 = r3b + (((m0 + lr)*132 + lc) << 2);
        uint32_t yad1 = yad0 + (16*132 << 2);
        float4 acc[2][2];
#pragma unroll
        for (int mm = 0; mm < 2; mm++)
#pragma unroll
            for (int tt = 0; tt < 2; tt++) acc[mm][tt] = make_float4(0.f,0.f,0.f,0.f);
#pragma unroll 4
        for (int k = 0; k < 16; k++){
            uint32_t a0, a1, a2, a3, c0, c1, c2, c3;
            ldsm4(a0, a1, a2, a3, yad0 + k*32);
            ldsm4(c0, c1, c2, c3, yad1 + k*32);
#pragma unroll
            for (int tt = 0; tt < 2; tt++){
                int tile = tp*2 + tt;
                float4 bw = __ldg(wop4 + tile*512 + k*32 + lane);
                uint32_t bh0 = __float_as_uint(bw.x), bh1 = __float_as_uint(bw.y);
                uint32_t bl0 = __float_as_uint(bw.z), bl1 = __float_as_uint(bw.w);
                mma8(acc[0][tt], a0, a1, a2, a3, bh0, bh1);
                mma8(acc[0][tt], a0, a1, a2, a3, bl0, bl1);
                mma8(acc[1][tt], c0, c1, c2, c3, bh0, bh1);
                mma8(acc[1][tt], c0, c1, c2, c3, bl0, bl1);
            }
        }
#pragma unroll
        for (int mm = 0; mm < 2; mm++){
            int pA = m0 + mm*16 + row_, pB = pA + 8;
#pragma unroll
            for (int tt = 0; tt < 2; tt++){
                int e = (tp*2 + tt)*8 + 2*col_;
                *(float2*)(mt + pA*132 + e) = make_float2(acc[mm][tt].x, acc[mm][tt].y);
                *(float2*)(mt + pB*132 + e) = make_float2(acc[mm][tt].z, acc[mm][tt].w);
            }
        }
    }
    __syncthreads();
    // phase 6: xt (tf32); LN stats
    {
        const float4* x4 = (const float4*)(x + base);
        for (int i = t; i < 64*32; i += 512){
            int p = i >> 5, q = i & 31;
            float4 v = x4[i];
            v.x = __uint_as_float(f2tf(v.x)); v.y = __uint_as_float(f2tf(v.y));
            v.z = __uint_as_float(f2tf(v.z)); v.w = __uint_as_float(f2tf(v.w));
            *(float4*)(xt + p*132 + q*4) = v;
        }
    }
    for (int p = warp*4; p < warp*4 + 4; p++){
        float4 v = *(const float4*)(mt + p*132 + lane*4);
        float s = v.x + v.y + v.z + v.w;
        s += __shfl_xor_sync(0xffffffffu, s, 16);
        s += __shfl_xor_sync(0xffffffffu, s, 8);
        s += __shfl_xor_sync(0xffffffffu, s, 4);
        s += __shfl_xor_sync(0xffffffffu, s, 2);
        s += __shfl_xor_sync(0xffffffffu, s, 1);
        float mu = s * (1.f/128.f);
        float dx = v.x - mu, dy = v.y - mu, dz = v.z - mu, dww = v.w - mu;
        float q = dx*dx + dy*dy + dz*dz + dww*dww;
        q += __shfl_xor_sync(0xffffffffu, q, 16);
        q += __shfl_xor_sync(0xffffffffu, q, 8);
        q += __shfl_xor_sync(0xffffffffu, q, 4);
        q += __shfl_xor_sync(0xffffffffu, q, 2);
        q += __shfl_xor_sync(0xffffffffu, q, 1);
        if (lane == 0){
            mus[p] = mu;
            rss[p] = rsqrtf(q * (1.f/128.f) + 1e-5f);
        }
    }
    __syncthreads();
    int p0 = (warp >> 2) * 16;
    int cq = warp & 3;
    int pA = p0 + row_, pB = pA + 8;
    // phase 7: gate GEMM + LN combine -> fs (r3, tf32)
    {
        uint32_t xtb = (uint32_t)__cvta_generic_to_shared(xt);
        uint32_t xad = xtb + (((p0 + lr)*132 + lc + cq*32) << 2);
        uint32_t af[4][4];
#pragma unroll
        for (int k = 0; k < 4; k++) ldsm4(af[k][0], af[k][1], af[k][2], af[k][3], xad + k*32);
#pragma unroll 1
        for (int nt = 0; nt < 4; nt++){
            int c0 = cq*32 + nt*8;
            int tile = cq*4 + nt;
            float4 acc = make_float4(0.f,0.f,0.f,0.f);
#pragma unroll
            for (int k = 0; k < 4; k++){
                float4 bw = __ldg(w2p4 + (tile*4 + k)*32 + lane);
                mma8(acc, af[k][0], af[k][1], af[k][2], af[k][3],
                     __float_as_uint(bw.x), __float_as_uint(bw.y));
                mma8(acc, af[k][0], af[k][1], af[k][2], af[k][3],
                     __float_as_uint(bw.z), __float_as_uint(bw.w));
            }
            int cc = c0 + 2*col_;
            float g0 = gb[cc], g1 = gb[cc + 1], b0 = gb[128 + cc], b1 = gb[128 + cc + 1];
            float vx = fmaf((mt[pA*132 + cc]     - mus[pA]) * rss[pA], g0, b0) * siluf(acc.x);
            float vy = fmaf((mt[pA*132 + cc + 1] - mus[pA]) * rss[pA], g1, b1) * siluf(acc.y);
            float vz = fmaf((mt[pB*132 + cc]     - mus[pB]) * rss[pB], g0, b0) * siluf(acc.z);
            float vw = fmaf((mt[pB*132 + cc + 1] - mus[pB]) * rss[pB], g1, b1) * siluf(acc.w);
            *(float2*)(r3 + pA*132 + cc) = make_float2(__uint_as_float(f2tf(vx)), __uint_as_float(f2tf(vy)));
            *(float2*)(r3 + pB*132 + cc) = make_float2(__uint_as_float(f2tf(vz)), __uint_as_float(f2tf(vw)));
        }
    }
    __syncwarp();
    // phase 8: final grouped1x1 -> out
    {
        uint32_t r3b = (uint32_t)__cvta_generic_to_shared(r3);
        uint32_t fad = r3b + (((p0 + lr)*132 + lc + cq*32) << 2);
        uint32_t af[4][4];
#pragma unroll
        for (int k = 0; k < 4; k++) ldsm4(af[k][0], af[k][1], af[k][2], af[k][3], fad + k*32);
#pragma unroll 1
        for (int nt = 0; nt < 4; nt++){
            int c0 = cq*32 + nt*8;
            int tile = cq*4 + nt;
            float4 acc = make_float4(0.f,0.f,0.f,0.f);
#pragma unroll
            for (int k = 0; k < 4; k++){
                float4 bw = __ldg(wtp4 + (tile*4 + k)*32 + lane);
                mma8(acc, af[k][0], af[k][1], af[k][2], af[k][3],
                     __float_as_uint(bw.x), __float_as_uint(bw.y));
                mma8(acc, af[k][0], af[k][1], af[k][2], af[k][3],
                     __float_as_uint(bw.z), __float_as_uint(bw.w));
            }
            int cc = c0 + 2*col_;
            *(float2*)(out + (size_t)(pix0 + pA)*128 + cc) = make_float2(acc.x, acc.y);
            *(float2*)(out + (size_t)(pix0 + pB)*128 + cc) = make_float2(acc.z, acc.w);
        }
    }
}

// ----------------------------------------------------------------
extern "C" void kernel_launch(void* const* d_in, const int* in_sizes, int n_in,
                              void* d_out, int out_size){
    const float* x        = (const float*)d_in[0];
    const float* w1       = (const float*)d_in[1];
    const float* dw       = (const float*)d_in[2];
    const float* in_proj  = (const float*)d_in[3];
    const float* conv1d_w = (const float*)d_in[4];
    const float* conv1d_b = (const float*)d_in[5];
    const float* x_proj_w = (const float*)d_in[6];
    const float* dt_proj_w= (const float*)d_in[7];
    const float* dt_proj_b= (const float*)d_in[8];
    const float* A_log    = (const float*)d_in[9];
    const float* D_param  = (const float*)d_in[10];
    const float* out_proj = (const float*)d_in[11];
    const float* gamma    = (const float*)d_in[12];
    const float* beta     = (const float*)d_in[13];
    const float* w2       = (const float*)d_in[14];
    const float* wout     = (const float*)d_in[15];
    float* out = (float*)d_out;

    float *t1, *xs, *u0, *z, *u, *dl, *Bm, *Cm, *Pg, *hE, *h0;
    float *wip, *wop, *w2p, *wtp, *wxp;
    cudaGetSymbolAddress((void**)&t1, g_t1);
    cudaGetSymbolAddress((void**)&xs, g_xs);
    cudaGetSymbolAddress((void**)&u0, g_u0);
    cudaGetSymbolAddress((void**)&z,  g_z);
    cudaGetSymbolAddress((void**)&u,  g_u);
    cudaGetSymbolAddress((void**)&dl, g_dl);
    cudaGetSymbolAddress((void**)&Bm, g_Bm);
    cudaGetSymbolAddress((void**)&Cm, g_Cm);
    cudaGetSymbolAddress((void**)&Pg, g_P);
    cudaGetSymbolAddress((void**)&hE, g_hE);
    cudaGetSymbolAddress((void**)&h0, g_h0);
    cudaGetSymbolAddress((void**)&wip, g_wip);
    cudaGetSymbolAddress((void**)&wop, g_wop);
    cudaGetSymbolAddress((void**)&w2p, g_w2p);
    cudaGetSymbolAddress((void**)&wtp, g_wtp);
    cudaGetSymbolAddress((void**)&wxp, g_wxp);

    const int smemI = (128*132) * sizeof(float);
    const int smemX = (8448 + 8448 + 64*XDS) * sizeof(float);
    const int smemM = (8448 + 8448 + 8448 + 512 + 512 + 64 + 64 + 256) * sizeof(float); // 104.5 KB
    static int attr_done = 0;
    if (!attr_done){
        cudaFuncSetAttribute(k_inproj, cudaFuncAttributeMaxDynamicSharedMemorySize, smemI);
        cudaFuncSetAttribute(k_cxp2,  cudaFuncAttributeMaxDynamicSharedMemorySize, smemX);
        cudaFuncSetAttribute(k_mega2, cudaFuncAttributeMaxDynamicSharedMemorySize, smemM);
        attr_done = 1;
    }

    k_prep<<<118, 256>>>(in_proj, out_proj, w2, wout, x_proj_w, wip, wop, w2p, wtp, wxp);
    k_g1<<<NPIX/32, 256>>>(x, w1, t1);
    k_dw<<<NPIX*32/256, 256>>>(t1, dw, xs);
    k_inproj<<<NPIX/128, 512, smemI>>>(xs, wip, u0, z);
    k_cxp2<<<NPIX/64, 512, smemX>>>(u0, conv1d_w, conv1d_b, wxp, dt_proj_w, dt_proj_b,
                                    A_log, u, dl, Bm, Cm, Pg, hE);
    k_scanB<<<64, 128>>>(Pg, hE, h0);
    k_mega2<<<BB*NC, 512, smemM>>>(dl, u, z, Bm, Cm, A_log, D_param, h0,
                                   wop, gamma, beta, x, w2p, wtp, out);
}

// round 16
// speedup vs baseline: 1.0347x; 1.0347x over previous
#include <cuda_runtime.h>
#include <math.h>
#include <stdint.h>

// Problem constants
#define BB 8
#define HH 64
#define WW 64
#define CC 128
#define DD 128
#define LL 4096            // H*W
#define NPIX (BB*LL)       // 32768
#define NS 8               // D_STATE
#define RR 8               // DT_RANK

#define CS 64              // chunk size (steps)
#define NC (LL/CS)         // 64 chunks per batch

// Scratch (device globals; no allocations allowed)
__device__ float g_t1[NPIX*DD];
__device__ float g_xs[NPIX*DD];
__device__ float g_u0[NPIX*DD];
__device__ float g_z [NPIX*DD];
__device__ float g_u [NPIX*DD];
__device__ float g_dl[NPIX*DD];
__device__ float g_Bm[NPIX*NS];
__device__ float g_Cm[NPIX*NS];
__device__ float g_P [BB*NC*1024];
__device__ float g_hE[BB*NC*1024];
__device__ float g_h0[BB*NC*1024];
// fragment-packed tf32 hi/lo weights: float4 {bh0, bh1, bl0, bl1} per (tile,k,lane)
__device__ float g_wip[65536];   // in_proj: 32 tiles x 16 k x 32 lanes
__device__ float g_wop[32768];   // out_proj: 16 tiles x 16 k x 32 lanes
__device__ float g_w2p[8192];    // w2 gate: 16 tiles x 4 k x 32 lanes
__device__ float g_wtp[8192];    // wout:    16 tiles x 4 k x 32 lanes
__device__ float g_wxp[6144];    // x_proj:  3 tiles x 16 k x 32 lanes
__device__ float g_w1p[8192];    // w1 g1x1: 16 tiles x 4 k x 32 lanes

__device__ __forceinline__ float siluf(float v){ return v / (1.f + __expf(-v)); }

__device__ __forceinline__ uint32_t f2tf(float x){
    uint32_t r; asm("cvt.rna.tf32.f32 %0, %1;" : "=r"(r) : "f"(x)); return r;
}
__device__ __forceinline__ void mma8(float4& c, uint32_t a0, uint32_t a1, uint32_t a2, uint32_t a3,
                                     uint32_t b0, uint32_t b1){
    asm volatile("mma.sync.aligned.m16n8k8.row.col.f32.tf32.tf32.f32 "
                 "{%0,%1,%2,%3},{%4,%5,%6,%7},{%8,%9},{%0,%1,%2,%3};\n"
                 : "+f"(c.x), "+f"(c.y), "+f"(c.z), "+f"(c.w)
                 : "r"(a0), "r"(a1), "r"(a2), "r"(a3), "r"(b0), "r"(b1));
}
__device__ __forceinline__ void ldsm4(uint32_t& r0, uint32_t& r1, uint32_t& r2, uint32_t& r3,
                                      uint32_t addr){
    asm volatile("ldmatrix.sync.aligned.m8n8.x4.shared.b16 {%0,%1,%2,%3}, [%4];"
                 : "=r"(r0), "=r"(r1), "=r"(r2), "=r"(r3) : "r"(addr));
}
__device__ __forceinline__ float4 pack_hl(float v0, float v1){
    float h0 = __uint_as_float(f2tf(v0));
    float h1 = __uint_as_float(f2tf(v1));
    return make_float4(h0, h1, v0 - h0, v1 - h1);
}

// ---------------------------------------------------------------- K0: weight fragment-pack prep
// segments (float4): wip 16384 | wop 8192 | w2p 2048 | wtp 2048 | wxp 1536 | w1p 2048 = 32256
__global__ void k_prep(const float* __restrict__ wi, const float* __restrict__ wo,
                       const float* __restrict__ w2, const float* __restrict__ wt,
                       const float* __restrict__ wx, const float* __restrict__ w1,
                       float* wip, float* wop, float* w2p, float* wtp, float* wxp, float* w1p){
    int i = blockIdx.x * 256 + threadIdx.x;
    if (i >= 32256) return;
    if (i < 16384){
        int lane = i & 31, k = (i >> 5) & 15, tile = i >> 9;
        int row = lane >> 2, col = lane & 3;
        int e = tile*8 + row, kc = k*8 + col;
        ((float4*)wip)[i] = pack_hl(wi[e*128 + kc], wi[e*128 + kc + 4]);
    } else if (i < 24576){
        int j = i - 16384;
        int lane = j & 31, k = (j >> 5) & 15, tile = j >> 9;
        int row = lane >> 2, col = lane & 3;
        int e = tile*8 + row, kc = k*8 + col;
        ((float4*)wop)[j] = pack_hl(wo[e*128 + kc], wo[e*128 + kc + 4]);
    } else if (i < 26624){
        int j = i - 24576;
        int lane = j & 31, k = (j >> 5) & 3, tile = j >> 7;
        int row = lane >> 2, col = lane & 3;
        int e = tile*8 + row;
        ((float4*)w2p)[j] = pack_hl(w2[e*32 + k*8 + col], w2[e*32 + k*8 + col + 4]);
    } else if (i < 28672){
        int j = i - 26624;
        int lane = j & 31, k = (j >> 5) & 3, tile = j >> 7;
        int row = lane >> 2, col = lane & 3;
        int e = tile*8 + row;
        ((float4*)wtp)[j] = pack_hl(wt[e*32 + k*8 + col], wt[e*32 + k*8 + col + 4]);
    } else if (i < 30208){
        int j = i - 28672;
        int lane = j & 31, k = (j >> 5) & 15, tile = j >> 9;
        int row = lane >> 2, col = lane & 3;
        int e = tile*8 + row, kc = k*8 + col;
        ((float4*)wxp)[j] = pack_hl(wx[e*128 + kc], wx[e*128 + kc + 4]);
    } else {
        int j = i - 30208;
        int lane = j & 31, k = (j >> 5) & 3, tile = j >> 7;
        int row = lane >> 2, col = lane & 3;
        int e = tile*8 + row;
        ((float4*)w1p)[j] = pack_hl(w1[e*32 + k*8 + col], w1[e*32 + k*8 + col + 4]);
    }
}

// ---------------------------------------------------------------- K1: grouped 1x1 via tf32 mma
// 256 thr (8 warps), 64 px/block, 512 blocks, 4 blocks/SM.
// warp = (m-pair p0 = (warp>>1)*16, channel-half th = warp&1 -> tiles th*8..th*8+7)
__global__ void __launch_bounds__(256, 4) k_g1(const float* __restrict__ x,
                                               const float* __restrict__ w1p,
                                               float* __restrict__ out){
    __shared__ float xt[64*132];
    int t = threadIdx.x, warp = t >> 5, lane = t & 31;
    int pix0 = blockIdx.x * 64;
    {
        const float4* x4 = (const float4*)(x + (size_t)pix0*128);
        for (int i = t; i < 64*32; i += 256){
            int p = i >> 5, q = i & 31;
            float4 v = x4[i];
            v.x = __uint_as_float(f2tf(v.x)); v.y = __uint_as_float(f2tf(v.y));
            v.z = __uint_as_float(f2tf(v.z)); v.w = __uint_as_float(f2tf(v.w));
            *(float4*)(xt + p*132 + q*4) = v;
        }
    }
    __syncthreads();
    int row_ = lane >> 2, col_ = lane & 3;
    int lr = lane & 15, lc = (lane >> 4) << 2;
    int p0 = (warp >> 1) * 16, th = warp & 1;
    uint32_t xtb = (uint32_t)__cvta_generic_to_shared(xt);
    uint32_t af[2][4][4];
#pragma unroll
    for (int gg = 0; gg < 2; gg++){
        int g = th*2 + gg;
        uint32_t xad = xtb + (((p0 + lr)*132 + g*32 + lc) << 2);
#pragma unroll
        for (int k = 0; k < 4; k++)
            ldsm4(af[gg][k][0], af[gg][k][1], af[gg][k][2], af[gg][k][3], xad + k*32);
    }
    const float4* w1p4 = (const float4*)w1p;
    int pA = p0 + row_, pB = pA + 8;
#pragma unroll 1
    for (int tt = 0; tt < 8; tt++){
        int tile = th*8 + tt;
        int gg = tt >> 2;
        float4 acc = make_float4(0.f,0.f,0.f,0.f);
#pragma unroll
        for (int k = 0; k < 4; k++){
            float4 bw = __ldg(w1p4 + (tile*4 + k)*32 + lane);
            mma8(acc, af[gg][k][0], af[gg][k][1], af[gg][k][2], af[gg][k][3],
                 __float_as_uint(bw.x), __float_as_uint(bw.y));
            mma8(acc, af[gg][k][0], af[gg][k][1], af[gg][k][2], af[gg][k][3],
                 __float_as_uint(bw.z), __float_as_uint(bw.w));
        }
        int cc = tile*8 + 2*col_;
        *(float2*)(out + (size_t)(pix0 + pA)*128 + cc) = make_float2(acc.x, acc.y);
        *(float2*)(out + (size_t)(pix0 + pB)*128 + cc) = make_float2(acc.z, acc.w);
    }
}

// ---------------------------------------------------------------- K2: depthwise 3x3 + silu
__global__ void k_dw(const float* __restrict__ t1, const float* __restrict__ dw,
                     float* __restrict__ out){
    int idx = blockIdx.x * 256 + threadIdx.x;
    int d4 = idx & 31; int pix = idx >> 5;
    int wc = pix & 63; int h = (pix >> 6) & 63; int b = pix >> 12;
    int d = d4 << 2;
    float4 acc = make_float4(0.f, 0.f, 0.f, 0.f);
#pragma unroll
    for (int kh = 0; kh < 3; kh++){
        int hh = h + kh - 1; if (hh < 0 || hh >= 64) continue;
#pragma unroll
        for (int kw = 0; kw < 3; kw++){
            int ww = wc + kw - 1; if (ww < 0 || ww >= 64) continue;
            float4 tv = *(const float4*)(t1 + (((b*64 + hh)*64 + ww) << 7) + d);
            float4 wv = *(const float4*)(dw + (kh*3 + kw)*128 + d);
            acc.x = fmaf(tv.x, wv.x, acc.x); acc.y = fmaf(tv.y, wv.y, acc.y);
            acc.z = fmaf(tv.z, wv.z, acc.z); acc.w = fmaf(tv.w, wv.w, acc.w);
        }
    }
    float4 r; r.x = siluf(acc.x); r.y = siluf(acc.y); r.z = siluf(acc.z); r.w = siluf(acc.w);
    *(float4*)(out + (size_t)pix*128 + d) = r;
}

// ---------------------------------------------------------------- K3: in_proj via tf32 mma (ldmatrix A, 2x2 tiles)
__global__ void __launch_bounds__(512, 2) k_inproj(const float* __restrict__ xs,
                       const float* __restrict__ wip,
                       float* __restrict__ ub, float* __restrict__ zb){
    extern __shared__ float sm[];
    float* xt = sm;              // 128*132
    int tid = threadIdx.x;
    int pix0 = blockIdx.x * 128;
    {
        const float4* xs4 = (const float4*)(xs + (size_t)pix0*128);
        for (int i = tid; i < 128*32; i += 512){
            int p = i >> 5, q = i & 31;
            float4 v = xs4[i];
            v.x = __uint_as_float(f2tf(v.x)); v.y = __uint_as_float(f2tf(v.y));
            v.z = __uint_as_float(f2tf(v.z)); v.w = __uint_as_float(f2tf(v.w));
            *(float4*)(xt + p*132 + q*4) = v;
        }
    }
    __syncthreads();
    int warp = tid >> 5, lane = tid & 31;
    int row_ = lane >> 2, col_ = lane & 3;
    int mp = warp >> 2, nq = warp & 3;
    int m0 = mp * 32;
    int lr = lane & 15, lc = (lane >> 4) << 2;
    uint32_t xtb = (uint32_t)__cvta_generic_to_shared(xt);
    uint32_t aad0 = xtb + (((m0 + lr)*132 + lc) << 2);
    uint32_t aad1 = aad0 + (16*132 << 2);
    const float4* wip4 = (const float4*)wip;
#pragma unroll 1
    for (int g = 0; g < 4; g++){
        float4 acc[2][2];
#pragma unroll
        for (int mm = 0; mm < 2; mm++)
#pragma unroll
            for (int tt = 0; tt < 2; tt++) acc[mm][tt] = make_float4(0.f,0.f,0.f,0.f);
#pragma unroll 4
        for (int k = 0; k < 16; k++){
            uint32_t a0, a1, a2, a3, c0, c1, c2, c3;
            ldsm4(a0, a1, a2, a3, aad0 + k*32);
            ldsm4(c0, c1, c2, c3, aad1 + k*32);
#pragma unroll
            for (int tt = 0; tt < 2; tt++){
                int tile = g*8 + nq*2 + tt;
                float4 bw = __ldg(wip4 + tile*512 + k*32 + lane);
                uint32_t bh0 = __float_as_uint(bw.x), bh1 = __float_as_uint(bw.y);
                uint32_t bl0 = __float_as_uint(bw.z), bl1 = __float_as_uint(bw.w);
                mma8(acc[0][tt], a0, a1, a2, a3, bh0, bh1);
                mma8(acc[0][tt], a0, a1, a2, a3, bl0, bl1);
                mma8(acc[1][tt], c0, c1, c2, c3, bh0, bh1);
                mma8(acc[1][tt], c0, c1, c2, c3, bl0, bl1);
            }
        }
#pragma unroll
        for (int mm = 0; mm < 2; mm++){
            int pixA = pix0 + m0 + mm*16 + row_;
            int pixB = pixA + 8;
#pragma unroll
            for (int tt = 0; tt < 2; tt++){
                int e0 = g*64 + (nq*2 + tt)*8 + 2*col_;
                float* basep = (g < 2) ? (ub + e0) : (zb + e0 - 128);
                *(float2*)(basep + (size_t)pixA*128) = make_float2(acc[mm][tt].x, acc[mm][tt].y);
                *(float2*)(basep + (size_t)pixB*128) = make_float2(acc[mm][tt].z, acc[mm][tt].w);
            }
        }
    }
}

// ---------------------------------------------------------------- K4: fused conv1d + x_proj(mma) + dt_proj + scanA
#define XDS 26
__global__ void __launch_bounds__(512, 2) k_cxp2(const float* __restrict__ u0,
                        const float* __restrict__ cw, const float* __restrict__ cb,
                        const float* __restrict__ wxp,
                        const float* __restrict__ dtw, const float* __restrict__ dtb,
                        const float* __restrict__ A_log,
                        float* __restrict__ ug,
                        float* __restrict__ dl, float* __restrict__ Bb, float* __restrict__ Cb,
                        float* __restrict__ Pg, float* __restrict__ hEg){
    extern __shared__ float sm[];
    float* u0s = sm;                 // 66*128 = 8448 ; aliased by sdl after conv
    float* su  = sm + 8448;          // 64*132
    float* xd  = sm + 16896;         // 64*XDS
    float* sdl = u0s;
    int pix0 = blockIdx.x * 64;
    int b = blockIdx.x >> 6;
    int c = blockIdx.x & 63;
    int l0 = pix0 & (LL - 1);
    int t = threadIdx.x, warp = t >> 5, lane = t & 31;
    {
        const float4* u4 = (const float4*)(u0 + ((size_t)pix0 - 2)*128);
        for (int i = t; i < 66*32; i += 512){
            int p = i >> 5;
            float4 v = make_float4(0.f,0.f,0.f,0.f);
            if (!(l0 == 0 && p < 2)) v = u4[i];
            ((float4*)u0s)[i] = v;
        }
    }
    __syncthreads();
    {
        int d = t & 127, ph = t >> 7;
        float w0 = cw[d*3], w1c = cw[d*3 + 1], w2c = cw[d*3 + 2];
        float bias = cb[d];
#pragma unroll 4
        for (int p = ph*16; p < ph*16 + 16; p++){
            float a = fmaf(w2c, u0s[(p + 2)*128 + d],
                      fmaf(w1c, u0s[(p + 1)*128 + d],
                      fmaf(w0,  u0s[p*128 + d], bias)));
            a = siluf(a);
            ug[(size_t)(pix0 + p)*128 + d] = a;
            su[p*132 + d] = a;
        }
    }
    __syncthreads();
    if (warp < 12){
        int m0 = (warp & 3) * 16;
        int ntile = warp >> 2;
        int row_ = lane >> 2, col_ = lane & 3;
        int lr = lane & 15, lc = (lane >> 4) << 2;
        uint32_t sub = (uint32_t)__cvta_generic_to_shared(su);
        uint32_t aad = sub + (((m0 + lr)*132 + lc) << 2);
        const float4* wxp4 = (const float4*)wxp;
        float4 acc = make_float4(0.f,0.f,0.f,0.f);
#pragma unroll 2
        for (int k = 0; k < 16; k++){
            uint32_t u0_, u1_, u2_, u3_;
            ldsm4(u0_, u1_, u2_, u3_, aad + k*32);
            float f0 = __uint_as_float(u0_), f1 = __uint_as_float(u1_);
            float f2 = __uint_as_float(u2_), f3 = __uint_as_float(u3_);
            uint32_t h0 = f2tf(f0), h1 = f2tf(f1), h2 = f2tf(f2), h3 = f2tf(f3);
            uint32_t l0_ = __float_as_uint(f0 - __uint_as_float(h0));
            uint32_t l1  = __float_as_uint(f1 - __uint_as_float(h1));
            uint32_t l2  = __float_as_uint(f2 - __uint_as_float(h2));
            uint32_t l3  = __float_as_uint(f3 - __uint_as_float(h3));
            float4 bw = __ldg(wxp4 + (ntile*16 + k)*32 + lane);
            uint32_t bh0 = __float_as_uint(bw.x), bh1 = __float_as_uint(bw.y);
            uint32_t bl0 = __float_as_uint(bw.z), bl1 = __float_as_uint(bw.w);
            mma8(acc, h0, h1, h2, h3, bh0, bh1);
            mma8(acc, h0, h1, h2, h3, bl0, bl1);
            mma8(acc, l0_, l1, l2, l3, bh0, bh1);
        }
        int pA = m0 + row_, pB = pA + 8;
        int cc = ntile*8 + 2*col_;
        *(float2*)(xd + pA*XDS + cc) = make_float2(acc.x, acc.y);
        *(float2*)(xd + pB*XDS + cc) = make_float2(acc.z, acc.w);
    }
    __syncthreads();
    {
        int d = t & 127, ph = t >> 7;
        float4 wa = ((const float4*)(dtw + d*8))[0];
        float4 wb = ((const float4*)(dtw + d*8))[1];
        float bias = dtb[d];
#pragma unroll 4
        for (int p = ph*16; p < ph*16 + 16; p++){
            const float* xr = xd + p*XDS;
            float a = bias;
            a = fmaf(xr[0], wa.x, a); a = fmaf(xr[1], wa.y, a);
            a = fmaf(xr[2], wa.z, a); a = fmaf(xr[3], wa.w, a);
            a = fmaf(xr[4], wb.x, a); a = fmaf(xr[5], wb.y, a);
            a = fmaf(xr[6], wb.z, a); a = fmaf(xr[7], wb.w, a);
            float sp = (a > 20.f) ? a : log1pf(__expf(a));
            dl[(size_t)(pix0 + p)*128 + d] = sp;
            sdl[p*128 + d] = sp;
        }
    }
    {
        int p = t >> 3, n = t & 7;
        Bb[(pix0 + p)*8 + n] = xd[p*XDS + 8 + n];
        Cb[(pix0 + p)*8 + n] = xd[p*XDS + 16 + n];
    }
    __syncthreads();
    {
        int d = t >> 2, np = (t & 3) * 2;
        float Av0 = -__expf(A_log[d*8 + np]);
        float Av1 = -__expf(A_log[d*8 + np + 1]);
        float h0 = 0.f, h1 = 0.f, P0 = 1.f, P1 = 1.f;
#pragma unroll 4
        for (int l = 0; l < CS; l++){
            float de = sdl[l*128 + d];
            float uu = su[l*132 + d];
            float du = de * uu;
            float2 Bv = *(const float2*)(xd + l*XDS + 8 + np);
            float dA0 = __expf(de * Av0);
            float dA1 = __expf(de * Av1);
            P0 *= dA0; P1 *= dA1;
            h0 = fmaf(dA0, h0, du * Bv.x);
            h1 = fmaf(dA1, h1, du * Bv.y);
        }
        size_t oidx = (size_t)(b*NC + c)*1024 + d*8 + np;
        *(float2*)(Pg + oidx) = make_float2(P0, P1);
        *(float2*)(hEg + oidx) = make_float2(h0, h1);
    }
}

// ---------------------------------------------------------------- K5: chunk combine (128 blocks x 64 thr)
__global__ void k_scanB(const float* __restrict__ Pg, const float* __restrict__ hEg,
                        float* __restrict__ h0g){
    int j = blockIdx.x * 64 + threadIdx.x;
    int b = j >> 10, dn = j & 1023;
    float h = 0.f;
#pragma unroll 8
    for (int c = 0; c < NC; c++){
        int idx = (b*NC + c)*1024 + dn;
        h0g[idx] = h;
        h = fmaf(Pg[idx], h, hEg[idx]);
    }
}

// ---------------------------------------------------------------- K6: MEGA2 = scanC + out_proj + LN + gate GEMMs
__global__ void __launch_bounds__(512, 2) k_mega2(
        const float* __restrict__ dl, const float* __restrict__ u,
        const float* __restrict__ z, const float* __restrict__ Bb,
        const float* __restrict__ Cb, const float* __restrict__ A_log,
        const float* __restrict__ Dp, const float* __restrict__ h0g,
        const float* __restrict__ wop,
        const float* __restrict__ gamma, const float* __restrict__ beta,
        const float* __restrict__ x,
        const float* __restrict__ w2p, const float* __restrict__ wtp,
        float* __restrict__ out){
    extern __shared__ float sm[];
    float* xt  = sm;              // 8448 (used phase 6+)
    float* r3  = sm + 8448;       // 8448: y -> fs
    float* mt  = sm + 16896;      // 8448
    float* sB  = sm + 25344;      // 512
    float* sC  = sB + 512;        // 512
    float* mus = sC + 512;        // 64
    float* rss = mus + 64;        // 64
    float* gb  = rss + 64;        // 256
    const float4* wop4 = (const float4*)wop;
    const float4* w2p4 = (const float4*)w2p;
    const float4* wtp4 = (const float4*)wtp;
    int b = blockIdx.x >> 6;
    int c = blockIdx.x & (NC - 1);
    int t = threadIdx.x, warp = t >> 5, lane = t & 31;
    int row_ = lane >> 2, col_ = lane & 3;
    int lr = lane & 15, lc = (lane >> 4) << 2;
    int pix0 = b*LL + c*CS;
    size_t base = (size_t)pix0*128;
    {
        int nb = pix0*8;
        if (t < CS*8){ sB[t] = Bb[nb + t]; sC[t] = Cb[nb + t]; }
        if (t < 128){ gb[t] = gamma[t]; gb[128 + t] = beta[t]; }
    }
    __syncthreads();
    {
        int d = t >> 2, np = (t & 3) * 2;
        float Av0 = -__expf(A_log[d*8 + np]);
        float Av1 = -__expf(A_log[d*8 + np + 1]);
        float2 h = *(const float2*)(h0g + (size_t)(b*NC + c)*1024 + d*8 + np);
        const float* dlp = dl + base + d;
        const float* up  = u + base + d;
#pragma unroll 4
        for (int l = 0; l < CS; l++){
            float de = __ldg(dlp + l*128);
            float uu = __ldg(up + l*128);
            float du = de * uu;
            float2 Bv = *(const float2*)(sB + l*8 + np);
            float2 Cv = *(const float2*)(sC + l*8 + np);
            h.x = fmaf(__expf(de * Av0), h.x, du * Bv.x);
            h.y = fmaf(__expf(de * Av1), h.y, du * Bv.y);
            float y = h.x * Cv.x + h.y * Cv.y;
            y += __shfl_xor_sync(0xffffffffu, y, 1);
            y += __shfl_xor_sync(0xffffffffu, y, 2);
            if ((t & 3) == 0) r3[l*132 + d] = y;
        }
    }
    __syncthreads();
    {
        for (int i = t; i < CS*128; i += 512){
            int l = i >> 7, d = i & 127;
            float val = fmaf(__ldg(u + base + i), Dp[d], r3[l*132 + d]);
            val *= siluf(z[base + i]);
            r3[l*132 + d] = __uint_as_float(f2tf(val));
        }
    }
    __syncthreads();
    {
        int mp = warp >> 3, tp = warp & 7;
        int m0 = mp * 32;
        uint32_t r3b = (uint32_t)__cvta_generic_to_shared(r3);
        uint32_t yad0 = r3b + (((m0 + lr)*132 + lc) << 2);
        uint32_t yad1 = yad0 + (16*132 << 2);
        float4 acc[2][2];
#pragma unroll
        for (int mm = 0; mm < 2; mm++)
#pragma unroll
            for (int tt = 0; tt < 2; tt++) acc[mm][tt] = make_float4(0.f,0.f,0.f,0.f);
#pragma unroll 4
        for (int k = 0; k < 16; k++){
            uint32_t a0, a1, a2, a3, c0, c1, c2, c3;
            ldsm4(a0, a1, a2, a3, yad0 + k*32);
            ldsm4(c0, c1, c2, c3, yad1 + k*32);
#pragma unroll
            for (int tt = 0; tt < 2; tt++){
                int tile = tp*2 + tt;
                float4 bw = __ldg(wop4 + tile*512 + k*32 + lane);
                uint32_t bh0 = __float_as_uint(bw.x), bh1 = __float_as_uint(bw.y);
                uint32_t bl0 = __float_as_uint(bw.z), bl1 = __float_as_uint(bw.w);
                mma8(acc[0][tt], a0, a1, a2, a3, bh0, bh1);
                mma8(acc[0][tt], a0, a1, a2, a3, bl0, bl1);
                mma8(acc[1][tt], c0, c1, c2, c3, bh0, bh1);
                mma8(acc[1][tt], c0, c1, c2, c3, bl0, bl1);
            }
        }
#pragma unroll
        for (int mm = 0; mm < 2; mm++){
            int pA = m0 + mm*16 + row_, pB = pA + 8;
#pragma unroll
            for (int tt = 0; tt < 2; tt++){
                int e = (tp*2 + tt)*8 + 2*col_;
                *(float2*)(mt + pA*132 + e) = make_float2(acc[mm][tt].x, acc[mm][tt].y);
                *(float2*)(mt + pB*132 + e) = make_float2(acc[mm][tt].z, acc[mm][tt].w);
            }
        }
    }
    __syncthreads();
    {
        const float4* x4 = (const float4*)(x + base);
        for (int i = t; i < 64*32; i += 512){
            int p = i >> 5, q = i & 31;
            float4 v = x4[i];
            v.x = __uint_as_float(f2tf(v.x)); v.y = __uint_as_float(f2tf(v.y));
            v.z = __uint_as_float(f2tf(v.z)); v.w = __uint_as_float(f2tf(v.w));
            *(float4*)(xt + p*132 + q*4) = v;
        }
    }
    for (int p = warp*4; p < warp*4 + 4; p++){
        float4 v = *(const float4*)(mt + p*132 + lane*4);
        float s = v.x + v.y + v.z + v.w;
        s += __shfl_xor_sync(0xffffffffu, s, 16);
        s += __shfl_xor_sync(0xffffffffu, s, 8);
        s += __shfl_xor_sync(0xffffffffu, s, 4);
        s += __shfl_xor_sync(0xffffffffu, s, 2);
        s += __shfl_xor_sync(0xffffffffu, s, 1);
        float mu = s * (1.f/128.f);
        float dx = v.x - mu, dy = v.y - mu, dz = v.z - mu, dww = v.w - mu;
        float q = dx*dx + dy*dy + dz*dz + dww*dww;
        q += __shfl_xor_sync(0xffffffffu, q, 16);
        q += __shfl_xor_sync(0xffffffffu, q, 8);
        q += __shfl_xor_sync(0xffffffffu, q, 4);
        q += __shfl_xor_sync(0xffffffffu, q, 2);
        q += __shfl_xor_sync(0xffffffffu, q, 1);
        if (lane == 0){
            mus[p] = mu;
            rss[p] = rsqrtf(q * (1.f/128.f) + 1e-5f);
        }
    }
    __syncthreads();
    int p0 = (warp >> 2) * 16;
    int cq = warp & 3;
    int pA = p0 + row_, pB = pA + 8;
    {
        uint32_t xtb = (uint32_t)__cvta_generic_to_shared(xt);
        uint32_t xad = xtb + (((p0 + lr)*132 + lc + cq*32) << 2);
        uint32_t af[4][4];
#pragma unroll
        for (int k = 0; k < 4; k++) ldsm4(af[k][0], af[k][1], af[k][2], af[k][3], xad + k*32);
#pragma unroll 1
        for (int nt = 0; nt < 4; nt++){
            int c0 = cq*32 + nt*8;
            int tile = cq*4 + nt;
            float4 acc = make_float4(0.f,0.f,0.f,0.f);
#pragma unroll
            for (int k = 0; k < 4; k++){
                float4 bw = __ldg(w2p4 + (tile*4 + k)*32 + lane);
                mma8(acc, af[k][0], af[k][1], af[k][2], af[k][3],
                     __float_as_uint(bw.x), __float_as_uint(bw.y));
                mma8(acc, af[k][0], af[k][1], af[k][2], af[k][3],
                     __float_as_uint(bw.z), __float_as_uint(bw.w));
            }
            int cc = c0 + 2*col_;
            float g0 = gb[cc], g1 = gb[cc + 1], b0 = gb[128 + cc], b1 = gb[128 + cc + 1];
            float vx = fmaf((mt[pA*132 + cc]     - mus[pA]) * rss[pA], g0, b0) * siluf(acc.x);
            float vy = fmaf((mt[pA*132 + cc + 1] - mus[pA]) * rss[pA], g1, b1) * siluf(acc.y);
            float vz = fmaf((mt[pB*132 + cc]     - mus[pB]) * rss[pB], g0, b0) * siluf(acc.z);
            float vw = fmaf((mt[pB*132 + cc + 1] - mus[pB]) * rss[pB], g1, b1) * siluf(acc.w);
            *(float2*)(r3 + pA*132 + cc) = make_float2(__uint_as_float(f2tf(vx)), __uint_as_float(f2tf(vy)));
            *(float2*)(r3 + pB*132 + cc) = make_float2(__uint_as_float(f2tf(vz)), __uint_as_float(f2tf(vw)));
        }
    }
    __syncwarp();
    {
        uint32_t r3b = (uint32_t)__cvta_generic_to_shared(r3);
        uint32_t fad = r3b + (((p0 + lr)*132 + lc + cq*32) << 2);
        uint32_t af[4][4];
#pragma unroll
        for (int k = 0; k < 4; k++) ldsm4(af[k][0], af[k][1], af[k][2], af[k][3], fad + k*32);
#pragma unroll 1
        for (int nt = 0; nt < 4; nt++){
            int c0 = cq*32 + nt*8;
            int tile = cq*4 + nt;
            float4 acc = make_float4(0.f,0.f,0.f,0.f);
#pragma unroll
            for (int k = 0; k < 4; k++){
                float4 bw = __ldg(wtp4 + (tile*4 + k)*32 + lane);
                mma8(acc, af[k][0], af[k][1], af[k][2], af[k][3],
                     __float_as_uint(bw.x), __float_as_uint(bw.y));
                mma8(acc, af[k][0], af[k][1], af[k][2], af[k][3],
                     __float_as_uint(bw.z), __float_as_uint(bw.w));
            }
            int cc = c0 + 2*col_;
            *(float2*)(out + (size_t)(pix0 + pA)*128 + cc) = make_float2(acc.x, acc.y);
            *(float2*)(out + (size_t)(pix0 + pB)*128 + cc) = make_float2(acc.z, acc.w);
        }
    }
}

// ----------------------------------------------------------------
extern "C" void kernel_launch(void* const* d_in, const int* in_sizes, int n_in,
                              void* d_out, int out_size){
    const float* x        = (const float*)d_in[0];
    const float* w1       = (const float*)d_in[1];
    const float* dw       = (const float*)d_in[2];
    const float* in_proj  = (const float*)d_in[3];
    const float* conv1d_w = (const float*)d_in[4];
    const float* conv1d_b = (const float*)d_in[5];
    const float* x_proj_w = (const float*)d_in[6];
    const float* dt_proj_w= (const float*)d_in[7];
    const float* dt_proj_b= (const float*)d_in[8];
    const float* A_log    = (const float*)d_in[9];
    const float* D_param  = (const float*)d_in[10];
    const float* out_proj = (const float*)d_in[11];
    const float* gamma    = (const float*)d_in[12];
    const float* beta     = (const float*)d_in[13];
    const float* w2       = (const float*)d_in[14];
    const float* wout     = (const float*)d_in[15];
    float* out = (float*)d_out;

    float *t1, *xs, *u0, *z, *u, *dl, *Bm, *Cm, *Pg, *hE, *h0;
    float *wip, *wop, *w2p, *wtp, *wxp, *w1p;
    cudaGetSymbolAddress((void**)&t1, g_t1);
    cudaGetSymbolAddress((void**)&xs, g_xs);
    cudaGetSymbolAddress((void**)&u0, g_u0);
    cudaGetSymbolAddress((void**)&z,  g_z);
    cudaGetSymbolAddress((void**)&u,  g_u);
    cudaGetSymbolAddress((void**)&dl, g_dl);
    cudaGetSymbolAddress((void**)&Bm, g_Bm);
    cudaGetSymbolAddress((void**)&Cm, g_Cm);
    cudaGetSymbolAddress((void**)&Pg, g_P);
    cudaGetSymbolAddress((void**)&hE, g_hE);
    cudaGetSymbolAddress((void**)&h0, g_h0);
    cudaGetSymbolAddress((void**)&wip, g_wip);
    cudaGetSymbolAddress((void**)&wop, g_wop);
    cudaGetSymbolAddress((void**)&w2p, g_w2p);
    cudaGetSymbolAddress((void**)&wtp, g_wtp);
    cudaGetSymbolAddress((void**)&wxp, g_wxp);
    cudaGetSymbolAddress((void**)&w1p, g_w1p);

    const int smemI = (128*132) * sizeof(float);
    const int smemX = (8448 + 8448 + 64*XDS) * sizeof(float);
    const int smemM = (8448 + 8448 + 8448 + 512 + 512 + 64 + 64 + 256) * sizeof(float); // 104.5 KB
    static int attr_done = 0;
    if (!attr_done){
        cudaFuncSetAttribute(k_inproj, cudaFuncAttributeMaxDynamicSharedMemorySize, smemI);
        cudaFuncSetAttribute(k_cxp2,  cudaFuncAttributeMaxDynamicSharedMemorySize, smemX);
        cudaFuncSetAttribute(k_mega2, cudaFuncAttributeMaxDynamicSharedMemorySize, smemM);
        attr_done = 1;
    }

    k_prep<<<126, 256>>>(in_proj, out_proj, w2, wout, x_proj_w, w1,
                         wip, wop, w2p, wtp, wxp, w1p);
    k_g1<<<NPIX/64, 256>>>(x, w1p, t1);
    k_dw<<<NPIX*32/256, 256>>>(t1, dw, xs);
    k_inproj<<<NPIX/128, 512, smemI>>>(xs, wip, u0, z);
    k_cxp2<<<NPIX/64, 512, smemX>>>(u0, conv1d_w, conv1d_b, wxp, dt_proj_w, dt_proj_b,
                                    A_log, u, dl, Bm, Cm, Pg, hE);
    k_scanB<<<128, 64>>>(Pg, hE, h0);
    k_mega2<<<BB*NC, 512, smemM>>>(dl, u, z, Bm, Cm, A_log, D_param, h0,
                                   wop, gamma, beta, x, w2p, wtp, out);
}

// round 17
// speedup vs baseline: 1.0454x; 1.0103x over previous
#include <cuda_runtime.h>
#include <math.h>
#include <stdint.h>

// Problem constants
#define BB 8
#define HH 64
#define WW 64
#define CC 128
#define DD 128
#define LL 4096            // H*W
#define NPIX (BB*LL)       // 32768
#define NS 8               // D_STATE
#define RR 8               // DT_RANK

#define CS 64              // chunk size (steps)
#define NC (LL/CS)         // 64 chunks per batch

// Scratch (device globals; no allocations allowed)
__device__ float g_t1[NPIX*DD];
__device__ float g_xs[NPIX*DD];
__device__ float g_u0[NPIX*DD];
__device__ float g_z [NPIX*DD];
__device__ float g_u [NPIX*DD];
__device__ float g_dl[NPIX*DD];
__device__ float g_Bm[NPIX*NS];
__device__ float g_Cm[NPIX*NS];
__device__ float g_P [BB*NC*1024];
__device__ float g_hE[BB*NC*1024];
__device__ float g_h0[BB*NC*1024];
// fragment-packed tf32 hi/lo weights: float4 {bh0, bh1, bl0, bl1} per (tile,k,lane)
__device__ float g_wip[65536];   // in_proj: 32 tiles x 16 k x 32 lanes
__device__ float g_wop[32768];   // out_proj: 16 tiles x 16 k x 32 lanes
__device__ float g_w2p[8192];    // w2 gate: 16 tiles x 4 k x 32 lanes
__device__ float g_wtp[8192];    // wout:    16 tiles x 4 k x 32 lanes
__device__ float g_wxp[6144];    // x_proj:  3 tiles x 16 k x 32 lanes
__device__ float g_w1p[8192];    // w1 g1x1: 16 tiles x 4 k x 32 lanes

__device__ __forceinline__ float siluf(float v){ return v / (1.f + __expf(-v)); }

__device__ __forceinline__ uint32_t f2tf(float x){
    uint32_t r; asm("cvt.rna.tf32.f32 %0, %1;" : "=r"(r) : "f"(x)); return r;
}
__device__ __forceinline__ void mma8(float4& c, uint32_t a0, uint32_t a1, uint32_t a2, uint32_t a3,
                                     uint32_t b0, uint32_t b1){
    asm volatile("mma.sync.aligned.m16n8k8.row.col.f32.tf32.tf32.f32 "
                 "{%0,%1,%2,%3},{%4,%5,%6,%7},{%8,%9},{%0,%1,%2,%3};\n"
                 : "+f"(c.x), "+f"(c.y), "+f"(c.z), "+f"(c.w)
                 : "r"(a0), "r"(a1), "r"(a2), "r"(a3), "r"(b0), "r"(b1));
}
__device__ __forceinline__ void ldsm4(uint32_t& r0, uint32_t& r1, uint32_t& r2, uint32_t& r3,
                                      uint32_t addr){
    asm volatile("ldmatrix.sync.aligned.m8n8.x4.shared.b16 {%0,%1,%2,%3}, [%4];"
                 : "=r"(r0), "=r"(r1), "=r"(r2), "=r"(r3) : "r"(addr));
}
__device__ __forceinline__ float4 pack_hl(float v0, float v1){
    float h0 = __uint_as_float(f2tf(v0));
    float h1 = __uint_as_float(f2tf(v1));
    return make_float4(h0, h1, v0 - h0, v1 - h1);
}

// ---------------------------------------------------------------- K0: weight fragment-pack prep
__global__ void k_prep(const float* __restrict__ wi, const float* __restrict__ wo,
                       const float* __restrict__ w2, const float* __restrict__ wt,
                       const float* __restrict__ wx, const float* __restrict__ w1,
                       float* wip, float* wop, float* w2p, float* wtp, float* wxp, float* w1p){
    int i = blockIdx.x * 256 + threadIdx.x;
    if (i >= 32256) return;
    if (i < 16384){
        int lane = i & 31, k = (i >> 5) & 15, tile = i >> 9;
        int row = lane >> 2, col = lane & 3;
        int e = tile*8 + row, kc = k*8 + col;
        ((float4*)wip)[i] = pack_hl(wi[e*128 + kc], wi[e*128 + kc + 4]);
    } else if (i < 24576){
        int j = i - 16384;
        int lane = j & 31, k = (j >> 5) & 15, tile = j >> 9;
        int row = lane >> 2, col = lane & 3;
        int e = tile*8 + row, kc = k*8 + col;
        ((float4*)wop)[j] = pack_hl(wo[e*128 + kc], wo[e*128 + kc + 4]);
    } else if (i < 26624){
        int j = i - 24576;
        int lane = j & 31, k = (j >> 5) & 3, tile = j >> 7;
        int row = lane >> 2, col = lane & 3;
        int e = tile*8 + row;
        ((float4*)w2p)[j] = pack_hl(w2[e*32 + k*8 + col], w2[e*32 + k*8 + col + 4]);
    } else if (i < 28672){
        int j = i - 26624;
        int lane = j & 31, k = (j >> 5) & 3, tile = j >> 7;
        int row = lane >> 2, col = lane & 3;
        int e = tile*8 + row;
        ((float4*)wtp)[j] = pack_hl(wt[e*32 + k*8 + col], wt[e*32 + k*8 + col + 4]);
    } else if (i < 30208){
        int j = i - 28672;
        int lane = j & 31, k = (j >> 5) & 15, tile = j >> 9;
        int row = lane >> 2, col = lane & 3;
        int e = tile*8 + row, kc = k*8 + col;
        ((float4*)wxp)[j] = pack_hl(wx[e*128 + kc], wx[e*128 + kc + 4]);
    } else {
        int j = i - 30208;
        int lane = j & 31, k = (j >> 5) & 3, tile = j >> 7;
        int row = lane >> 2, col = lane & 3;
        int e = tile*8 + row;
        ((float4*)w1p)[j] = pack_hl(w1[e*32 + k*8 + col], w1[e*32 + k*8 + col + 4]);
    }
}

// ---------------------------------------------------------------- K1: grouped 1x1 via tf32 mma
__global__ void __launch_bounds__(256, 4) k_g1(const float* __restrict__ x,
                                               const float* __restrict__ w1p,
                                               float* __restrict__ out){
    __shared__ float xt[64*132];
    int t = threadIdx.x, warp = t >> 5, lane = t & 31;
    int pix0 = blockIdx.x * 64;
    {
        const float4* x4 = (const float4*)(x + (size_t)pix0*128);
        for (int i = t; i < 64*32; i += 256){
            int p = i >> 5, q = i & 31;
            float4 v = x4[i];
            v.x = __uint_as_float(f2tf(v.x)); v.y = __uint_as_float(f2tf(v.y));
            v.z = __uint_as_float(f2tf(v.z)); v.w = __uint_as_float(f2tf(v.w));
            *(float4*)(xt + p*132 + q*4) = v;
        }
    }
    __syncthreads();
    int row_ = lane >> 2, col_ = lane & 3;
    int lr = lane & 15, lc = (lane >> 4) << 2;
    int p0 = (warp >> 1) * 16, th = warp & 1;
    uint32_t xtb = (uint32_t)__cvta_generic_to_shared(xt);
    uint32_t af[2][4][4];
#pragma unroll
    for (int gg = 0; gg < 2; gg++){
        int g = th*2 + gg;
        uint32_t xad = xtb + (((p0 + lr)*132 + g*32 + lc) << 2);
#pragma unroll
        for (int k = 0; k < 4; k++)
            ldsm4(af[gg][k][0], af[gg][k][1], af[gg][k][2], af[gg][k][3], xad + k*32);
    }
    const float4* w1p4 = (const float4*)w1p;
    int pA = p0 + row_, pB = pA + 8;
#pragma unroll 1
    for (int tt = 0; tt < 8; tt++){
        int tile = th*8 + tt;
        int gg = tt >> 2;
        float4 acc = make_float4(0.f,0.f,0.f,0.f);
#pragma unroll
        for (int k = 0; k < 4; k++){
            float4 bw = __ldg(w1p4 + (tile*4 + k)*32 + lane);
            mma8(acc, af[gg][k][0], af[gg][k][1], af[gg][k][2], af[gg][k][3],
                 __float_as_uint(bw.x), __float_as_uint(bw.y));
            mma8(acc, af[gg][k][0], af[gg][k][1], af[gg][k][2], af[gg][k][3],
                 __float_as_uint(bw.z), __float_as_uint(bw.w));
        }
        int cc = tile*8 + 2*col_;
        *(float2*)(out + (size_t)(pix0 + pA)*128 + cc) = make_float2(acc.x, acc.y);
        *(float2*)(out + (size_t)(pix0 + pB)*128 + cc) = make_float2(acc.z, acc.w);
    }
}

// ---------------------------------------------------------------- K2: depthwise 3x3 + silu
__global__ void k_dw(const float* __restrict__ t1, const float* __restrict__ dw,
                     float* __restrict__ out){
    int idx = blockIdx.x * 256 + threadIdx.x;
    int d4 = idx & 31; int pix = idx >> 5;
    int wc = pix & 63; int h = (pix >> 6) & 63; int b = pix >> 12;
    int d = d4 << 2;
    float4 acc = make_float4(0.f, 0.f, 0.f, 0.f);
#pragma unroll
    for (int kh = 0; kh < 3; kh++){
        int hh = h + kh - 1; if (hh < 0 || hh >= 64) continue;
#pragma unroll
        for (int kw = 0; kw < 3; kw++){
            int ww = wc + kw - 1; if (ww < 0 || ww >= 64) continue;
            float4 tv = *(const float4*)(t1 + (((b*64 + hh)*64 + ww) << 7) + d);
            float4 wv = *(const float4*)(dw + (kh*3 + kw)*128 + d);
            acc.x = fmaf(tv.x, wv.x, acc.x); acc.y = fmaf(tv.y, wv.y, acc.y);
            acc.z = fmaf(tv.z, wv.z, acc.z); acc.w = fmaf(tv.w, wv.w, acc.w);
        }
    }
    float4 r; r.x = siluf(acc.x); r.y = siluf(acc.y); r.z = siluf(acc.z); r.w = siluf(acc.w);
    *(float4*)(out + (size_t)pix*128 + d) = r;
}

// ---------------------------------------------------------------- K3: in_proj via tf32 mma (hi/lo split issue)
__global__ void __launch_bounds__(512, 2) k_inproj(const float* __restrict__ xs,
                       const float* __restrict__ wip,
                       float* __restrict__ ub, float* __restrict__ zb){
    extern __shared__ float sm[];
    float* xt = sm;              // 128*132
    int tid = threadIdx.x;
    int pix0 = blockIdx.x * 128;
    {
        const float4* xs4 = (const float4*)(xs + (size_t)pix0*128);
        for (int i = tid; i < 128*32; i += 512){
            int p = i >> 5, q = i & 31;
            float4 v = xs4[i];
            v.x = __uint_as_float(f2tf(v.x)); v.y = __uint_as_float(f2tf(v.y));
            v.z = __uint_as_float(f2tf(v.z)); v.w = __uint_as_float(f2tf(v.w));
            *(float4*)(xt + p*132 + q*4) = v;
        }
    }
    __syncthreads();
    int warp = tid >> 5, lane = tid & 31;
    int row_ = lane >> 2, col_ = lane & 3;
    int mp = warp >> 2, nq = warp & 3;
    int m0 = mp * 32;
    int lr = lane & 15, lc = (lane >> 4) << 2;
    uint32_t xtb = (uint32_t)__cvta_generic_to_shared(xt);
    uint32_t aad0 = xtb + (((m0 + lr)*132 + lc) << 2);
    uint32_t aad1 = aad0 + (16*132 << 2);
    const float4* wip4 = (const float4*)wip;
#pragma unroll 1
    for (int g = 0; g < 4; g++){
        float4 acc[2][2];
#pragma unroll
        for (int mm = 0; mm < 2; mm++)
#pragma unroll
            for (int tt = 0; tt < 2; tt++) acc[mm][tt] = make_float4(0.f,0.f,0.f,0.f);
#pragma unroll 4
        for (int k = 0; k < 16; k++){
            uint32_t a0, a1, a2, a3, c0, c1, c2, c3;
            ldsm4(a0, a1, a2, a3, aad0 + k*32);
            ldsm4(c0, c1, c2, c3, aad1 + k*32);
            float4 bw0 = __ldg(wip4 + (g*8 + nq*2)*512 + k*32 + lane);
            float4 bw1 = __ldg(wip4 + (g*8 + nq*2 + 1)*512 + k*32 + lane);
            // hi pass (4 independent mma), then lo pass (per-acc order hi->lo preserved)
            mma8(acc[0][0], a0, a1, a2, a3, __float_as_uint(bw0.x), __float_as_uint(bw0.y));
            mma8(acc[0][1], a0, a1, a2, a3, __float_as_uint(bw1.x), __float_as_uint(bw1.y));
            mma8(acc[1][0], c0, c1, c2, c3, __float_as_uint(bw0.x), __float_as_uint(bw0.y));
            mma8(acc[1][1], c0, c1, c2, c3, __float_as_uint(bw1.x), __float_as_uint(bw1.y));
            mma8(acc[0][0], a0, a1, a2, a3, __float_as_uint(bw0.z), __float_as_uint(bw0.w));
            mma8(acc[0][1], a0, a1, a2, a3, __float_as_uint(bw1.z), __float_as_uint(bw1.w));
            mma8(acc[1][0], c0, c1, c2, c3, __float_as_uint(bw0.z), __float_as_uint(bw0.w));
            mma8(acc[1][1], c0, c1, c2, c3, __float_as_uint(bw1.z), __float_as_uint(bw1.w));
        }
#pragma unroll
        for (int mm = 0; mm < 2; mm++){
            int pixA = pix0 + m0 + mm*16 + row_;
            int pixB = pixA + 8;
#pragma unroll
            for (int tt = 0; tt < 2; tt++){
                int e0 = g*64 + (nq*2 + tt)*8 + 2*col_;
                float* basep = (g < 2) ? (ub + e0) : (zb + e0 - 128);
                *(float2*)(basep + (size_t)pixA*128) = make_float2(acc[mm][tt].x, acc[mm][tt].y);
                *(float2*)(basep + (size_t)pixB*128) = make_float2(acc[mm][tt].z, acc[mm][tt].w);
            }
        }
    }
}

// ---------------------------------------------------------------- K4: fused conv1d + x_proj(mma, 3-acc) + dt_proj + scanA
#define XDS 26
__global__ void __launch_bounds__(512, 2) k_cxp2(const float* __restrict__ u0,
                        const float* __restrict__ cw, const float* __restrict__ cb,
                        const float* __restrict__ wxp,
                        const float* __restrict__ dtw, const float* __restrict__ dtb,
                        const float* __restrict__ A_log,
                        float* __restrict__ ug,
                        float* __restrict__ dl, float* __restrict__ Bb, float* __restrict__ Cb,
                        float* __restrict__ Pg, float* __restrict__ hEg){
    extern __shared__ float sm[];
    float* u0s = sm;                 // 66*128 = 8448 ; aliased by sdl after conv
    float* su  = sm + 8448;          // 64*132
    float* xd  = sm + 16896;         // 64*XDS
    float* sdl = u0s;
    int pix0 = blockIdx.x * 64;
    int b = blockIdx.x >> 6;
    int c = blockIdx.x & 63;
    int l0 = pix0 & (LL - 1);
    int t = threadIdx.x, warp = t >> 5, lane = t & 31;
    {
        const float4* u4 = (const float4*)(u0 + ((size_t)pix0 - 2)*128);
        for (int i = t; i < 66*32; i += 512){
            int p = i >> 5;
            float4 v = make_float4(0.f,0.f,0.f,0.f);
            if (!(l0 == 0 && p < 2)) v = u4[i];
            ((float4*)u0s)[i] = v;
        }
    }
    __syncthreads();
    {
        int d = t & 127, ph = t >> 7;
        float w0 = cw[d*3], w1c = cw[d*3 + 1], w2c = cw[d*3 + 2];
        float bias = cb[d];
#pragma unroll 4
        for (int p = ph*16; p < ph*16 + 16; p++){
            float a = fmaf(w2c, u0s[(p + 2)*128 + d],
                      fmaf(w1c, u0s[(p + 1)*128 + d],
                      fmaf(w0,  u0s[p*128 + d], bias)));
            a = siluf(a);
            ug[(size_t)(pix0 + p)*128 + d] = a;
            su[p*132 + d] = a;
        }
    }
    __syncthreads();
    if (warp < 12){
        int m0 = (warp & 3) * 16;
        int ntile = warp >> 2;
        int row_ = lane >> 2, col_ = lane & 3;
        int lr = lane & 15, lc = (lane >> 4) << 2;
        uint32_t sub = (uint32_t)__cvta_generic_to_shared(su);
        uint32_t aad = sub + (((m0 + lr)*132 + lc) << 2);
        const float4* wxp4 = (const float4*)wxp;
        float4 accA = make_float4(0.f,0.f,0.f,0.f);
        float4 accB = make_float4(0.f,0.f,0.f,0.f);
        float4 accC = make_float4(0.f,0.f,0.f,0.f);
#pragma unroll 2
        for (int k = 0; k < 16; k++){
            uint32_t u0_, u1_, u2_, u3_;
            ldsm4(u0_, u1_, u2_, u3_, aad + k*32);
            float f0 = __uint_as_float(u0_), f1 = __uint_as_float(u1_);
            float f2 = __uint_as_float(u2_), f3 = __uint_as_float(u3_);
            uint32_t h0 = f2tf(f0), h1 = f2tf(f1), h2 = f2tf(f2), h3 = f2tf(f3);
            uint32_t l0_ = __float_as_uint(f0 - __uint_as_float(h0));
            uint32_t l1  = __float_as_uint(f1 - __uint_as_float(h1));
            uint32_t l2  = __float_as_uint(f2 - __uint_as_float(h2));
            uint32_t l3  = __float_as_uint(f3 - __uint_as_float(h3));
            float4 bw = __ldg(wxp4 + (ntile*16 + k)*32 + lane);
            uint32_t bh0 = __float_as_uint(bw.x), bh1 = __float_as_uint(bw.y);
            uint32_t bl0 = __float_as_uint(bw.z), bl1 = __float_as_uint(bw.w);
            mma8(accA, h0, h1, h2, h3, bh0, bh1);
            mma8(accB, h0, h1, h2, h3, bl0, bl1);
            mma8(accC, l0_, l1, l2, l3, bh0, bh1);
        }
        float4 acc;
        acc.x = (accA.x + accB.x) + accC.x;
        acc.y = (accA.y + accB.y) + accC.y;
        acc.z = (accA.z + accB.z) + accC.z;
        acc.w = (accA.w + accB.w) + accC.w;
        int pA = m0 + row_, pB = pA + 8;
        int cc = ntile*8 + 2*col_;
        *(float2*)(xd + pA*XDS + cc) = make_float2(acc.x, acc.y);
        *(float2*)(xd + pB*XDS + cc) = make_float2(acc.z, acc.w);
    }
    __syncthreads();
    {
        int d = t & 127, ph = t >> 7;
        float4 wa = ((const float4*)(dtw + d*8))[0];
        float4 wb = ((const float4*)(dtw + d*8))[1];
        float bias = dtb[d];
#pragma unroll 4
        for (int p = ph*16; p < ph*16 + 16; p++){
            const float* xr = xd + p*XDS;
            float a = bias;
            a = fmaf(xr[0], wa.x, a); a = fmaf(xr[1], wa.y, a);
            a = fmaf(xr[2], wa.z, a); a = fmaf(xr[3], wa.w, a);
            a = fmaf(xr[4], wb.x, a); a = fmaf(xr[5], wb.y, a);
            a = fmaf(xr[6], wb.z, a); a = fmaf(xr[7], wb.w, a);
            float sp = (a > 20.f) ? a : log1pf(__expf(a));
            dl[(size_t)(pix0 + p)*128 + d] = sp;
            sdl[p*128 + d] = sp;
        }
    }
    {
        int p = t >> 3, n = t & 7;
        Bb[(pix0 + p)*8 + n] = xd[p*XDS + 8 + n];
        Cb[(pix0 + p)*8 + n] = xd[p*XDS + 16 + n];
    }
    __syncthreads();
    {
        int d = t >> 2, np = (t & 3) * 2;
        float Av0 = -__expf(A_log[d*8 + np]);
        float Av1 = -__expf(A_log[d*8 + np + 1]);
        float h0 = 0.f, h1 = 0.f, P0 = 1.f, P1 = 1.f;
#pragma unroll 4
        for (int l = 0; l < CS; l++){
            float de = sdl[l*128 + d];
            float uu = su[l*132 + d];
            float du = de * uu;
            float2 Bv = *(const float2*)(xd + l*XDS + 8 + np);
            float dA0 = __expf(de * Av0);
            float dA1 = __expf(de * Av1);
            P0 *= dA0; P1 *= dA1;
            h0 = fmaf(dA0, h0, du * Bv.x);
            h1 = fmaf(dA1, h1, du * Bv.y);
        }
        size_t oidx = (size_t)(b*NC + c)*1024 + d*8 + np;
        *(float2*)(Pg + oidx) = make_float2(P0, P1);
        *(float2*)(hEg + oidx) = make_float2(h0, h1);
    }
}

// ---------------------------------------------------------------- K5: chunk combine (128 blocks x 64 thr)
__global__ void k_scanB(const float* __restrict__ Pg, const float* __restrict__ hEg,
                        float* __restrict__ h0g){
    int j = blockIdx.x * 64 + threadIdx.x;
    int b = j >> 10, dn = j & 1023;
    float h = 0.f;
#pragma unroll 8
    for (int c = 0; c < NC; c++){
        int idx = (b*NC + c)*1024 + dn;
        h0g[idx] = h;
        h = fmaf(Pg[idx], h, hEg[idx]);
    }
}

// ---------------------------------------------------------------- K6: MEGA2 = scanC + out_proj + LN + gate GEMMs
__global__ void __launch_bounds__(512, 2) k_mega2(
        const float* __restrict__ dl, const float* __restrict__ u,
        const float* __restrict__ z, const float* __restrict__ Bb,
        const float* __restrict__ Cb, const float* __restrict__ A_log,
        const float* __restrict__ Dp, const float* __restrict__ h0g,
        const float* __restrict__ wop,
        const float* __restrict__ gamma, const float* __restrict__ beta,
        const float* __restrict__ x,
        const float* __restrict__ w2p, const float* __restrict__ wtp,
        float* __restrict__ out){
    extern __shared__ float sm[];
    float* xt  = sm;              // 8448 (used phase 6+)
    float* r3  = sm + 8448;       // 8448: y -> fs
    float* mt  = sm + 16896;      // 8448
    float* sB  = sm + 25344;      // 512
    float* sC  = sB + 512;        // 512
    float* mus = sC + 512;        // 64
    float* rss = mus + 64;        // 64
    float* gb  = rss + 64;        // 256
    const float4* wop4 = (const float4*)wop;
    const float4* w2p4 = (const float4*)w2p;
    const float4* wtp4 = (const float4*)wtp;
    int b = blockIdx.x >> 6;
    int c = blockIdx.x & (NC - 1);
    int t = threadIdx.x, warp = t >> 5, lane = t & 31;
    int row_ = lane >> 2, col_ = lane & 3;
    int lr = lane & 15, lc = (lane >> 4) << 2;
    int pix0 = b*LL + c*CS;
    size_t base = (size_t)pix0*128;
    {
        int nb = pix0*8;
        if (t < CS*8){ sB[t] = Bb[nb + t]; sC[t] = Cb[nb + t]; }
        if (t < 128){ gb[t] = gamma[t]; gb[128 + t] = beta[t]; }
    }
    __syncthreads();
    {
        int d = t >> 2, np = (t & 3) * 2;
        float Av0 = -__expf(A_log[d*8 + np]);
        float Av1 = -__expf(A_log[d*8 + np + 1]);
        float2 h = *(const float2*)(h0g + (size_t)(b*NC + c)*1024 + d*8 + np);
        const float* dlp = dl + base + d;
        const float* up  = u + base + d;
#pragma unroll 4
        for (int l = 0; l < CS; l++){
            float de = __ldg(dlp + l*128);
            float uu = __ldg(up + l*128);
            float du = de * uu;
            float2 Bv = *(const float2*)(sB + l*8 + np);
            float2 Cv = *(const float2*)(sC + l*8 + np);
            h.x = fmaf(__expf(de * Av0), h.x, du * Bv.x);
            h.y = fmaf(__expf(de * Av1), h.y, du * Bv.y);
            float y = h.x * Cv.x + h.y * Cv.y;
            y += __shfl_xor_sync(0xffffffffu, y, 1);
            y += __shfl_xor_sync(0xffffffffu, y, 2);
            if ((t & 3) == 0) r3[l*132 + d] = y;
        }
    }
    __syncthreads();
    {
        for (int i = t; i < CS*128; i += 512){
            int l = i >> 7, d = i & 127;
            float val = fmaf(__ldg(u + base + i), Dp[d], r3[l*132 + d]);
            val *= siluf(z[base + i]);
            r3[l*132 + d] = __uint_as_float(f2tf(val));
        }
    }
    __syncthreads();
    // phase 5: out_proj GEMM (hi/lo split issue)
    {
        int mp = warp >> 3, tp = warp & 7;
        int m0 = mp * 32;
        uint32_t r3b = (uint32_t)__cvta_generic_to_shared(r3);
        uint32_t yad0 = r3b + (((m0 + lr)*132 + lc) << 2);
        uint32_t yad1 = yad0 + (16*132 << 2);
        float4 acc[2][2];
#pragma unroll
        for (int mm = 0; mm < 2; mm++)
#pragma unroll
            for (int tt = 0; tt < 2; tt++) acc[mm][tt] = make_float4(0.f,0.f,0.f,0.f);
#pragma unroll 4
        for (int k = 0; k < 16; k++){
            uint32_t a0, a1, a2, a3, c0, c1, c2, c3;
            ldsm4(a0, a1, a2, a3, yad0 + k*32);
            ldsm4(c0, c1, c2, c3, yad1 + k*32);
            float4 bw0 = __ldg(wop4 + (tp*2)*512 + k*32 + lane);
            float4 bw1 = __ldg(wop4 + (tp*2 + 1)*512 + k*32 + lane);
            mma8(acc[0][0], a0, a1, a2, a3, __float_as_uint(bw0.x), __float_as_uint(bw0.y));
            mma8(acc[0][1], a0, a1, a2, a3, __float_as_uint(bw1.x), __float_as_uint(bw1.y));
            mma8(acc[1][0], c0, c1, c2, c3, __float_as_uint(bw0.x), __float_as_uint(bw0.y));
            mma8(acc[1][1], c0, c1, c2, c3, __float_as_uint(bw1.x), __float_as_uint(bw1.y));
            mma8(acc[0][0], a0, a1, a2, a3, __float_as_uint(bw0.z), __float_as_uint(bw0.w));
            mma8(acc[0][1], a0, a1, a2, a3, __float_as_uint(bw1.z), __float_as_uint(bw1.w));
            mma8(acc[1][0], c0, c1, c2, c3, __float_as_uint(bw0.z), __float_as_uint(bw0.w));
            mma8(acc[1][1], c0, c1, c2, c3, __float_as_uint(bw1.z), __float_as_uint(bw1.w));
        }
#pragma unroll
        for (int mm = 0; mm < 2; mm++){
            int pA = m0 + mm*16 + row_, pB = pA + 8;
#pragma unroll
            for (int tt = 0; tt < 2; tt++){
                int e = (tp*2 + tt)*8 + 2*col_;
                *(float2*)(mt + pA*132 + e) = make_float2(acc[mm][tt].x, acc[mm][tt].y);
                *(float2*)(mt + pB*132 + e) = make_float2(acc[mm][tt].z, acc[mm][tt].w);
            }
        }
    }
    __syncthreads();
    {
        const float4* x4 = (const float4*)(x + base);
        for (int i = t; i < 64*32; i += 512){
            int p = i >> 5, q = i & 31;
            float4 v = x4[i];
            v.x = __uint_as_float(f2tf(v.x)); v.y = __uint_as_float(f2tf(v.y));
            v.z = __uint_as_float(f2tf(v.z)); v.w = __uint_as_float(f2tf(v.w));
            *(float4*)(xt + p*132 + q*4) = v;
        }
    }
    for (int p = warp*4; p < warp*4 + 4; p++){
        float4 v = *(const float4*)(mt + p*132 + lane*4);
        float s = v.x + v.y + v.z + v.w;
        s += __shfl_xor_sync(0xffffffffu, s, 16);
        s += __shfl_xor_sync(0xffffffffu, s, 8);
        s += __shfl_xor_sync(0xffffffffu, s, 4);
        s += __shfl_xor_sync(0xffffffffu, s, 2);
        s += __shfl_xor_sync(0xffffffffu, s, 1);
        float mu = s * (1.f/128.f);
        float dx = v.x - mu, dy = v.y - mu, dz = v.z - mu, dww = v.w - mu;
        float q = dx*dx + dy*dy + dz*dz + dww*dww;
        q += __shfl_xor_sync(0xffffffffu, q, 16);
        q += __shfl_xor_sync(0xffffffffu, q, 8);
        q += __shfl_xor_sync(0xffffffffu, q, 4);
        q += __shfl_xor_sync(0xffffffffu, q, 2);
        q += __shfl_xor_sync(0xffffffffu, q, 1);
        if (lane == 0){
            mus[p] = mu;
            rss[p] = rsqrtf(q * (1.f/128.f) + 1e-5f);
        }
    }
    __syncthreads();
    int p0 = (warp >> 2) * 16;
    int cq = warp & 3;
    int pA = p0 + row_, pB = pA + 8;
    {
        uint32_t xtb = (uint32_t)__cvta_generic_to_shared(xt);
        uint32_t xad = xtb + (((p0 + lr)*132 + lc + cq*32) << 2);
        uint32_t af[4][4];
#pragma unroll
        for (int k = 0; k < 4; k++) ldsm4(af[k][0], af[k][1], af[k][2], af[k][3], xad + k*32);
#pragma unroll 1
        for (int nt = 0; nt < 4; nt++){
            int c0 = cq*32 + nt*8;
            int tile = cq*4 + nt;
            float4 acc = make_float4(0.f,0.f,0.f,0.f);
#pragma unroll
            for (int k = 0; k < 4; k++){
                float4 bw = __ldg(w2p4 + (tile*4 + k)*32 + lane);
                mma8(acc, af[k][0], af[k][1], af[k][2], af[k][3],
                     __float_as_uint(bw.x), __float_as_uint(bw.y));
                mma8(acc, af[k][0], af[k][1], af[k][2], af[k][3],
                     __float_as_uint(bw.z), __float_as_uint(bw.w));
            }
            int cc = c0 + 2*col_;
            float g0 = gb[cc], g1 = gb[cc + 1], b0 = gb[128 + cc], b1 = gb[128 + cc + 1];
            float vx = fmaf((mt[pA*132 + cc]     - mus[pA]) * rss[pA], g0, b0) * siluf(acc.x);
            float vy = fmaf((mt[pA*132 + cc + 1] - mus[pA]) * rss[pA], g1, b1) * siluf(acc.y);
            float vz = fmaf((mt[pB*132 + cc]     - mus[pB]) * rss[pB], g0, b0) * siluf(acc.z);
            float vw = fmaf((mt[pB*132 + cc + 1] - mus[pB]) * rss[pB], g1, b1) * siluf(acc.w);
            *(float2*)(r3 + pA*132 + cc) = make_float2(__uint_as_float(f2tf(vx)), __uint_as_float(f2tf(vy)));
            *(float2*)(r3 + pB*132 + cc) = make_float2(__uint_as_float(f2tf(vz)), __uint_as_float(f2tf(vw)));
        }
    }
    __syncwarp();
    {
        uint32_t r3b = (uint32_t)__cvta_generic_to_shared(r3);
        uint32_t fad = r3b + (((p0 + lr)*132 + lc + cq*32) << 2);
        uint32_t af[4][4];
#pragma unroll
        for (int k = 0; k < 4; k++) ldsm4(af[k][0], af[k][1], af[k][2], af[k][3], fad + k*32);
#pragma unroll 1
        for (int nt = 0; nt < 4; nt++){
            int c0 = cq*32 + nt*8;
            int tile = cq*4 + nt;
            float4 acc = make_float4(0.f,0.f,0.f,0.f);
#pragma unroll
            for (int k = 0; k < 4; k++){
                float4 bw = __ldg(wtp4 + (tile*4 + k)*32 + lane);
                mma8(acc, af[k][0], af[k][1], af[k][2], af[k][3],
                     __float_as_uint(bw.x), __float_as_uint(bw.y));
                mma8(acc, af[k][0], af[k][1], af[k][2], af[k][3],
                     __float_as_uint(bw.z), __float_as_uint(bw.w));
            }
            int cc = c0 + 2*col_;
            *(float2*)(out + (size_t)(pix0 + pA)*128 + cc) = make_float2(acc.x, acc.y);
            *(float2*)(out + (size_t)(pix0 + pB)*128 + cc) = make_float2(acc.z, acc.w);
        }
    }
}

// ----------------------------------------------------------------
extern "C" void kernel_launch(void* const* d_in, const int* in_sizes, int n_in,
                              void* d_out, int out_size){
    const float* x        = (const float*)d_in[0];
    const float* w1       = (const float*)d_in[1];
    const float* dw       = (const float*)d_in[2];
    const float* in_proj  = (const float*)d_in[3];
    const float* conv1d_w = (const float*)d_in[4];
    const float* conv1d_b = (const float*)d_in[5];
    const float* x_proj_w = (const float*)d_in[6];
    const float* dt_proj_w= (const float*)d_in[7];
    const float* dt_proj_b= (const float*)d_in[8];
    const float* A_log    = (const float*)d_in[9];
    const float* D_param  = (const float*)d_in[10];
    const float* out_proj = (const float*)d_in[11];
    const float* gamma    = (const float*)d_in[12];
    const float* beta     = (const float*)d_in[13];
    const float* w2       = (const float*)d_in[14];
    const float* wout     = (const float*)d_in[15];
    float* out = (float*)d_out;

    float *t1, *xs, *u0, *z, *u, *dl, *Bm, *Cm, *Pg, *hE, *h0;
    float *wip, *wop, *w2p, *wtp, *wxp, *w1p;
    cudaGetSymbolAddress((void**)&t1, g_t1);
    cudaGetSymbolAddress((void**)&xs, g_xs);
    cudaGetSymbolAddress((void**)&u0, g_u0);
    cudaGetSymbolAddress((void**)&z,  g_z);
    cudaGetSymbolAddress((void**)&u,  g_u);
    cudaGetSymbolAddress((void**)&dl, g_dl);
    cudaGetSymbolAddress((void**)&Bm, g_Bm);
    cudaGetSymbolAddress((void**)&Cm, g_Cm);
    cudaGetSymbolAddress((void**)&Pg, g_P);
    cudaGetSymbolAddress((void**)&hE, g_hE);
    cudaGetSymbolAddress((void**)&h0, g_h0);
    cudaGetSymbolAddress((void**)&wip, g_wip);
    cudaGetSymbolAddress((void**)&wop, g_wop);
    cudaGetSymbolAddress((void**)&w2p, g_w2p);
    cudaGetSymbolAddress((void**)&wtp, g_wtp);
    cudaGetSymbolAddress((void**)&wxp, g_wxp);
    cudaGetSymbolAddress((void**)&w1p, g_w1p);

    const int smemI = (128*132) * sizeof(float);
    const int smemX = (8448 + 8448 + 64*XDS) * sizeof(float);
    const int smemM = (8448 + 8448 + 8448 + 512 + 512 + 64 + 64 + 256) * sizeof(float);
    static int attr_done = 0;
    if (!attr_done){
        cudaFuncSetAttribute(k_inproj, cudaFuncAttributeMaxDynamicSharedMemorySize, smemI);
        cudaFuncSetAttribute(k_cxp2,  cudaFuncAttributeMaxDynamicSharedMemorySize, smemX);
        cudaFuncSetAttribute(k_mega2, cudaFuncAttributeMaxDynamicSharedMemorySize, smemM);
        attr_done = 1;
    }

    k_prep<<<126, 256>>>(in_proj, out_proj, w2, wout, x_proj_w, w1,
                         wip, wop, w2p, wtp, wxp, w1p);
    k_g1<<<NPIX/64, 256>>>(x, w1p, t1);
    k_dw<<<NPIX*32/256, 256>>>(t1, dw, xs);
    k_inproj<<<NPIX/128, 512, smemI>>>(xs, wip, u0, z);
    k_cxp2<<<NPIX/64, 512, smemX>>>(u0, conv1d_w, conv1d_b, wxp, dt_proj_w, dt_proj_b,
                                    A_log, u, dl, Bm, Cm, Pg, hE);
    k_scanB<<<128, 64>>>(Pg, hE, h0);
    k_mega2<<<BB*NC, 512, smemM>>>(dl, u, z, Bm, Cm, A_log, D_param, h0,
                                   wop, gamma, beta, x, w2p, wtp, out);
}